// round 3
// baseline (speedup 1.0000x reference)
#include <cuda_runtime.h>

// Problem constants (shapes fixed by the dataset)
#define NOBJ_MAX 50000
#define NEVT_MAX 100000
#define NEDGE_MAX 500000
#define DIM 256

// ---------------- static scratch (no allocations allowed) ----------------
__device__ float g_Y[NEVT_MAX * DIM];        // relu(event_X @ Wp^T + bp)
__device__ float g_profile[NOBJ_MAX * DIM];  // compact scatter-mean rows
__device__ float g_GI[NOBJ_MAX * 768];
__device__ float g_GH[NOBJ_MAX * 768];
__device__ int   g_cnt[NOBJ_MAX];
__device__ int   g_off[NOBJ_MAX];
__device__ int   g_cur[NOBJ_MAX];
__device__ int   g_mask[NOBJ_MAX];
__device__ int   g_list[NOBJ_MAX];
__device__ int   g_sortedEvt[NEDGE_MAX];
__device__ int   g_bsum[64];
__device__ int   g_nm;

// ---------------- small utility kernels ----------------
__global__ void k_zero(int n_obj) {
    int i = blockIdx.x * blockDim.x + threadIdx.x;
    if (i < n_obj) { g_cnt[i] = 0; g_cur[i] = 0; g_mask[i] = 0; }
    if (i == 0) g_nm = 0;
}

__global__ void k_count(const int* __restrict__ obj, int n) {
    int i = blockIdx.x * blockDim.x + threadIdx.x;
    if (i < n) atomicAdd(&g_cnt[obj[i]], 1);
}

__global__ void k_scan1(int n) {
    __shared__ int s[1024];
    int t = threadIdx.x;
    int i = blockIdx.x * 1024 + t;
    int v = (i < n) ? g_cnt[i] : 0;
    s[t] = v; __syncthreads();
    for (int d = 1; d < 1024; d <<= 1) {
        int x = (t >= d) ? s[t - d] : 0;
        __syncthreads();
        s[t] += x;
        __syncthreads();
    }
    if (i < n) g_off[i] = s[t] - v;
    if (t == 1023) g_bsum[blockIdx.x] = s[1023];
}

__global__ void k_scan2(int nb) {
    if (threadIdx.x == 0 && blockIdx.x == 0) {
        int run = 0;
        for (int b = 0; b < nb; b++) { int t = g_bsum[b]; g_bsum[b] = run; run += t; }
    }
}

__global__ void k_scan3(int n) {
    int i = blockIdx.x * blockDim.x + threadIdx.x;
    if (i < n) g_off[i] += g_bsum[i >> 10];
}

__global__ void k_fill(const int* __restrict__ obj, const int* __restrict__ evt, int n) {
    int i = blockIdx.x * blockDim.x + threadIdx.x;
    if (i < n) {
        int o = obj[i];
        int p = atomicAdd(&g_cur[o], 1);
        g_sortedEvt[g_off[o] + p] = evt[i];
    }
}

// compact unique masked objects into g_list (order irrelevant)
__global__ void k_list(const int* __restrict__ midx, int n) {
    int i = blockIdx.x * blockDim.x + threadIdx.x;
    if (i < n) {
        int o = midx[i];
        if (atomicExch(&g_mask[o], 1) == 0) {
            int p = atomicAdd(&g_nm, 1);
            g_list[p] = o;
        }
    }
}

// ---------------- fp32 tiled GEMM: C = A @ W^T + bias (optional relu) ----------------
// A: [M,K] row-major (optionally row-gathered via rowIdx), W: [N,K] row-major.
// BM=BN=64, BK=16, 256 threads, 4x4 register tile per thread.
template <int RELU>
__global__ __launch_bounds__(256) void k_gemm(
    const float* __restrict__ A, const float* __restrict__ W,
    const float* __restrict__ bias, float* __restrict__ C,
    int M, int N, int K,
    const int* __restrict__ rowIdx, const int* __restrict__ dM)
{
    __shared__ float As[16][64];
    __shared__ float Ws[16][64];

    int Meff = dM ? *dM : M;
    int m0 = blockIdx.y * 64;
    if (m0 >= Meff) return;
    int n0 = blockIdx.x * 64;

    int tid = threadIdx.x;
    int lr = tid >> 2;          // load row within tile (0..63)
    int lc = (tid & 3) << 2;    // load col within k-slab (0,4,8,12)
    int tr = tid >> 4;          // compute row group (0..15)
    int tc = tid & 15;          // compute col group (0..15)

    const float* Aptr = nullptr;
    {
        int r = m0 + lr;
        if (r < Meff) {
            int ar = rowIdx ? rowIdx[r] : r;
            Aptr = A + (long long)ar * K;
        }
    }
    const float* Wptr = W + (long long)(n0 + lr) * K;

    float acc[4][4];
#pragma unroll
    for (int i = 0; i < 4; i++)
#pragma unroll
        for (int j = 0; j < 4; j++) acc[i][j] = 0.f;

    for (int kt = 0; kt < K; kt += 16) {
        float4 av = make_float4(0.f, 0.f, 0.f, 0.f);
        if (Aptr) av = *(const float4*)(Aptr + kt + lc);
        float4 wv = *(const float4*)(Wptr + kt + lc);
        As[lc + 0][lr] = av.x; As[lc + 1][lr] = av.y;
        As[lc + 2][lr] = av.z; As[lc + 3][lr] = av.w;
        Ws[lc + 0][lr] = wv.x; Ws[lc + 1][lr] = wv.y;
        Ws[lc + 2][lr] = wv.z; Ws[lc + 3][lr] = wv.w;
        __syncthreads();
#pragma unroll
        for (int k = 0; k < 16; k++) {
            float4 a = *(const float4*)&As[k][tr << 2];
            float4 b = *(const float4*)&Ws[k][tc << 2];
            acc[0][0] += a.x * b.x; acc[0][1] += a.x * b.y; acc[0][2] += a.x * b.z; acc[0][3] += a.x * b.w;
            acc[1][0] += a.y * b.x; acc[1][1] += a.y * b.y; acc[1][2] += a.y * b.z; acc[1][3] += a.y * b.w;
            acc[2][0] += a.z * b.x; acc[2][1] += a.z * b.y; acc[2][2] += a.z * b.z; acc[2][3] += a.z * b.w;
            acc[3][0] += a.w * b.x; acc[3][1] += a.w * b.y; acc[3][2] += a.w * b.z; acc[3][3] += a.w * b.w;
        }
        __syncthreads();
    }

#pragma unroll
    for (int i = 0; i < 4; i++) {
        int r = m0 + (tr << 2) + i;
        if (r >= Meff) continue;
#pragma unroll
        for (int j = 0; j < 4; j++) {
            int c = n0 + (tc << 2) + j;
            float v = acc[i][j] + bias[c];
            if (RELU) v = fmaxf(v, 0.f);
            C[(long long)r * N + c] = v;
        }
    }
}

// ---------------- per-object scatter-mean gather (one warp per compact row) ----------------
__global__ void k_profile() {
    int w = (blockIdx.x * blockDim.x + threadIdx.x) >> 5;
    int lane = threadIdx.x & 31;
    if (w >= g_nm) return;
    int o = g_list[w];
    int beg = g_off[o];
    int c = g_cnt[o];
    float4 s0 = make_float4(0.f, 0.f, 0.f, 0.f);
    float4 s1 = make_float4(0.f, 0.f, 0.f, 0.f);
    const float4* Y4 = (const float4*)g_Y;
    for (int i = 0; i < c; i++) {
        int e = g_sortedEvt[beg + i];
        const float4* p = Y4 + (long long)e * 64 + lane * 2;
        float4 a = p[0], b = p[1];
        s0.x += a.x; s0.y += a.y; s0.z += a.z; s0.w += a.w;
        s1.x += b.x; s1.y += b.y; s1.z += b.z; s1.w += b.w;
    }
    float inv = 1.f / fmaxf((float)c, 1.f);
    s0.x *= inv; s0.y *= inv; s0.z *= inv; s0.w *= inv;
    s1.x *= inv; s1.y *= inv; s1.z *= inv; s1.w *= inv;
    float4* dst = (float4*)g_profile + (long long)w * 64 + lane * 2;
    dst[0] = s0; dst[1] = s1;
}

// ---------------- full pass-through copy out = object_X ----------------
__global__ void k_copy(const float* __restrict__ X, float* __restrict__ out, int n4) {
    int i = blockIdx.x * blockDim.x + threadIdx.x;
    if (i < n4) ((float4*)out)[i] = ((const float4*)X)[i];
}

// ---------------- fused GRU elementwise + masked write ----------------
__global__ void k_gru(const float* __restrict__ objX, float* __restrict__ out) {
    int r = blockIdx.x;
    if (r >= g_nm) return;
    int c = threadIdx.x;  // 256 threads
    int o = g_list[r];
    float h = objX[(long long)o * DIM + c];
    const float* gi = g_GI + (long long)r * 768;
    const float* gh = g_GH + (long long)r * 768;
    float ir = gi[c], iz = gi[c + 256], in_ = gi[c + 512];
    float hr = gh[c], hz = gh[c + 256], hn = gh[c + 512];
    float rg = 1.f / (1.f + __expf(-(ir + hr)));
    float z  = 1.f / (1.f + __expf(-(iz + hz)));
    float n  = tanhf(in_ + rg * hn);
    out[(long long)o * DIM + c] = (1.f - z) * n + z * h;
}

// ---------------- launch ----------------
extern "C" void kernel_launch(void* const* d_in, const int* in_sizes, int n_in,
                              void* d_out, int out_size) {
    const float* objX  = (const float*)d_in[0];
    const float* evtX  = (const float*)d_in[1];
    const int*   obj_i = (const int*)d_in[2];
    const int*   evt_i = (const int*)d_in[3];
    const int*   m_idx = (const int*)d_in[4];
    const float* Wp    = (const float*)d_in[5];
    const float* bp    = (const float*)d_in[6];
    const float* Wih   = (const float*)d_in[7];
    const float* bih   = (const float*)d_in[8];
    const float* Whh   = (const float*)d_in[9];
    const float* bhh   = (const float*)d_in[10];
    float* out = (float*)d_out;

    int n_obj  = in_sizes[0] / DIM;
    int n_evt  = in_sizes[1] / DIM;
    int n_edge = in_sizes[2];
    int n_main = in_sizes[4];

    // symbol addresses (pure queries; not stream ops)
    float *pY, *pProf, *pGI, *pGH;
    int *pList, *pNM;
    cudaGetSymbolAddress((void**)&pY, g_Y);
    cudaGetSymbolAddress((void**)&pProf, g_profile);
    cudaGetSymbolAddress((void**)&pGI, g_GI);
    cudaGetSymbolAddress((void**)&pGH, g_GH);
    cudaGetSymbolAddress((void**)&pList, g_list);
    cudaGetSymbolAddress((void**)&pNM, g_nm);

    // 1. zero bookkeeping
    k_zero<<<(n_obj + 255) / 256, 256>>>(n_obj);

    // 2. Y = relu(event_X @ Wp^T + bp)   [n_evt, 256]
    {
        dim3 g(DIM / 64, (n_evt + 63) / 64);
        k_gemm<1><<<g, 256>>>(evtX, Wp, bp, pY, n_evt, DIM, DIM, nullptr, nullptr);
    }

    // 3. CSR build
    k_count<<<(n_edge + 255) / 256, 256>>>(obj_i, n_edge);
    int nb = (n_obj + 1023) / 1024;
    k_scan1<<<nb, 1024>>>(n_obj);
    k_scan2<<<1, 32>>>(nb);
    k_scan3<<<(n_obj + 255) / 256, 256>>>(n_obj);
    k_fill<<<(n_edge + 255) / 256, 256>>>(obj_i, evt_i, n_edge);

    // 4. compact unique masked objects
    k_list<<<(n_main + 255) / 256, 256>>>(m_idx, n_main);

    // 5. scatter-mean gather for compact rows (1 warp / row, grid covers worst case)
    k_profile<<<(n_obj + 3) / 4, 128>>>();

    // 6. GRU GEMMs over compact rows only
    {
        dim3 g(768 / 64, (n_obj + 63) / 64);
        k_gemm<0><<<g, 256>>>(pProf, Wih, bih, pGI, n_obj, 768, DIM, nullptr, pNM);
        k_gemm<0><<<g, 256>>>(objX, Whh, bhh, pGH, n_obj, 768, DIM, pList, pNM);
    }

    // 7. pass-through copy, then overwrite masked rows with GRU output
    k_copy<<<(n_obj * (DIM / 4) + 255) / 256, 256>>>(objX, out, n_obj * (DIM / 4));
    k_gru<<<n_obj, DIM>>>(objX, out);
}

// round 8
// speedup vs baseline: 2.2877x; 2.2877x over previous
#include <cuda_runtime.h>
#include <cuda_bf16.h>
#include <cstdint>

#define NOBJ_MAX 50000
#define NEVT_MAX 100000
#define NEDGE_MAX 500000
#define DIM 256

// ---------------- static scratch ----------------
__device__ __align__(16) __nv_bfloat16 g_Ehi[NEVT_MAX * DIM];
__device__ __align__(16) __nv_bfloat16 g_Elo[NEVT_MAX * DIM];
__device__ __align__(16) float         g_Y[NEVT_MAX * DIM];
__device__ __align__(16) __nv_bfloat16 g_Phi[NOBJ_MAX * DIM];
__device__ __align__(16) __nv_bfloat16 g_Plo[NOBJ_MAX * DIM];
__device__ __align__(16) __nv_bfloat16 g_Ohi[NOBJ_MAX * DIM];
__device__ __align__(16) __nv_bfloat16 g_Olo[NOBJ_MAX * DIM];
__device__ __align__(16) __nv_bfloat16 g_Wphi[DIM * DIM];
__device__ __align__(16) __nv_bfloat16 g_Wplo[DIM * DIM];
__device__ __align__(16) __nv_bfloat16 g_WihHi[768 * DIM];
__device__ __align__(16) __nv_bfloat16 g_WihLo[768 * DIM];
__device__ __align__(16) __nv_bfloat16 g_WhhHi[768 * DIM];
__device__ __align__(16) __nv_bfloat16 g_WhhLo[768 * DIM];
__device__ __align__(16) float g_GI[NOBJ_MAX * 768];
__device__ __align__(16) float g_GH[NOBJ_MAX * 768];
__device__ int g_cnt[NOBJ_MAX];
__device__ int g_off[NOBJ_MAX];
__device__ int g_cur[NOBJ_MAX];
__device__ int g_mask[NOBJ_MAX];
__device__ int g_list[NOBJ_MAX];
__device__ int g_sortedEvt[NEDGE_MAX];
__device__ int g_bsum[64];
__device__ int g_nm;

// ---------------- PTX helpers (sm_80-portable only) ----------------
__device__ __forceinline__ uint32_t smem_to_u32(const void* p) {
    uint32_t a;
    asm("{ .reg .u64 t; cvta.to.shared.u64 t, %1; cvt.u32.u64 %0, t; }"
        : "=r"(a) : "l"(p));
    return a;
}
__device__ __forceinline__ void cp_async16(uint32_t dst, const void* src, int src_bytes) {
    asm volatile("cp.async.cg.shared.global [%0], [%1], 16, %2;"
                 :: "r"(dst), "l"(src), "r"(src_bytes) : "memory");
}
__device__ __forceinline__ void cp_commit() {
    asm volatile("cp.async.commit_group;" ::: "memory");
}
__device__ __forceinline__ void cp_wait0() {
    asm volatile("cp.async.wait_group 0;" ::: "memory");
}
__device__ __forceinline__ void ldsm_x4(uint32_t& r0, uint32_t& r1, uint32_t& r2, uint32_t& r3,
                                        uint32_t addr) {
    asm volatile("ldmatrix.sync.aligned.m8n8.x4.shared.b16 {%0,%1,%2,%3}, [%4];"
                 : "=r"(r0), "=r"(r1), "=r"(r2), "=r"(r3) : "r"(addr));
}
__device__ __forceinline__ void mma_bf16(float* d, const uint32_t* a,
                                         uint32_t b0, uint32_t b1) {
    asm volatile("mma.sync.aligned.m16n8k16.row.col.f32.bf16.bf16.f32 "
                 "{%0,%1,%2,%3}, {%4,%5,%6,%7}, {%8,%9}, {%0,%1,%2,%3};"
                 : "+f"(d[0]), "+f"(d[1]), "+f"(d[2]), "+f"(d[3])
                 : "r"(a[0]), "r"(a[1]), "r"(a[2]), "r"(a[3]), "r"(b0), "r"(b1));
}

#define SWZ(o) ((o) ^ (((o) >> 3) & 0x70))

// ---------------- bf16 hi/lo split helpers ----------------
__device__ __forceinline__ uint32_t bf2pack(float x, float y) {
    union { __nv_bfloat162 b; uint32_t u; } cv;
    cv.b.x = __float2bfloat16(x); cv.b.y = __float2bfloat16(y);
    return cv.u;
}
__device__ __forceinline__ void split2(float x, float y, uint32_t& h, uint32_t& l) {
    __nv_bfloat16 hx = __float2bfloat16(x), hy = __float2bfloat16(y);
    union { __nv_bfloat162 b; uint32_t u; } cv;
    cv.b.x = hx; cv.b.y = hy; h = cv.u;
    l = bf2pack(x - __bfloat162float(hx), y - __bfloat162float(hy));
}

// ---------------- small utility kernels ----------------
__global__ void k_zero(int n_obj) {
    int i = blockIdx.x * blockDim.x + threadIdx.x;
    if (i < n_obj) { g_cnt[i] = 0; g_cur[i] = 0; g_mask[i] = 0; }
    if (i == 0) g_nm = 0;
}
__global__ void k_count(const int* __restrict__ obj, int n) {
    int i = blockIdx.x * blockDim.x + threadIdx.x;
    if (i < n) atomicAdd(&g_cnt[obj[i]], 1);
}
__global__ void k_scan1(int n) {
    __shared__ int s[1024];
    int t = threadIdx.x;
    int i = blockIdx.x * 1024 + t;
    int v = (i < n) ? g_cnt[i] : 0;
    s[t] = v; __syncthreads();
    for (int d = 1; d < 1024; d <<= 1) {
        int x = (t >= d) ? s[t - d] : 0;
        __syncthreads();
        s[t] += x;
        __syncthreads();
    }
    if (i < n) g_off[i] = s[t] - v;
    if (t == 1023) g_bsum[blockIdx.x] = s[1023];
}
__global__ void k_scan2(int nb) {
    if (threadIdx.x == 0 && blockIdx.x == 0) {
        int run = 0;
        for (int b = 0; b < nb; b++) { int t = g_bsum[b]; g_bsum[b] = run; run += t; }
    }
}
__global__ void k_scan3(int n) {
    int i = blockIdx.x * blockDim.x + threadIdx.x;
    if (i < n) g_off[i] += g_bsum[i >> 10];
}
__global__ void k_fill(const int* __restrict__ obj, const int* __restrict__ evt, int n) {
    int i = blockIdx.x * blockDim.x + threadIdx.x;
    if (i < n) {
        int o = obj[i];
        int p = atomicAdd(&g_cur[o], 1);
        g_sortedEvt[g_off[o] + p] = evt[i];
    }
}
__global__ void k_list(const int* __restrict__ midx, int n) {
    int i = blockIdx.x * blockDim.x + threadIdx.x;
    if (i < n) {
        int o = midx[i];
        if (atomicExch(&g_mask[o], 1) == 0) {
            int p = atomicAdd(&g_nm, 1);
            g_list[p] = o;
        }
    }
}

// fp32 -> bf16 hi/lo elementwise (8 floats per thread)
__global__ void k_split(const float* __restrict__ x, __nv_bfloat16* __restrict__ hi,
                        __nv_bfloat16* __restrict__ lo, int n8) {
    int i = blockIdx.x * blockDim.x + threadIdx.x;
    if (i >= n8) return;
    float4 a = ((const float4*)x)[2 * i];
    float4 b = ((const float4*)x)[2 * i + 1];
    uint4 hv, lv;
    split2(a.x, a.y, hv.x, lv.x);
    split2(a.z, a.w, hv.y, lv.y);
    split2(b.x, b.y, hv.z, lv.z);
    split2(b.z, b.w, hv.w, lv.w);
    ((uint4*)hi)[i] = hv;
    ((uint4*)lo)[i] = lv;
}

// ---------------- mma.sync split-bf16 GEMM: C = A @ B^T + bias ----------------
// Block tile 128x128, K-chunk 64 (128B SW128 rows), 12 chunks = 3 passes
// (hi*hi, lo*hi, hi*lo) x 4. cp.async double buffer, 1 syncthreads/chunk.
// 8 warps: warp_m = wid&3 (32 rows), warp_n = wid>>2 (64 cols), warp tile 32x64.
template <int RELU>
__global__ __launch_bounds__(256) void k_tc(
    const __nv_bfloat16* __restrict__ Ahi, const __nv_bfloat16* __restrict__ Alo,
    const __nv_bfloat16* __restrict__ Bhi, const __nv_bfloat16* __restrict__ Blo,
    const float* __restrict__ bias, float* __restrict__ C,
    int M, const int* __restrict__ dM, int N)
{
    extern __shared__ __align__(1024) char dsm[];  // 2 x (16KB A + 16KB B)
    int Meff = dM ? *dM : M;
    int m0 = blockIdx.y * 128;
    if (m0 >= Meff) return;
    int n0 = blockIdx.x * 128;

    int tid = threadIdx.x, wid = tid >> 5, lane = tid & 31;
    int warp_m = wid & 3, warp_n = wid >> 2;
    uint32_t sb = smem_to_u32(dsm);

    int lrow = tid >> 1;   // 0..127
    int lhalf = tid & 1;   // 64B half of the 128B row

    auto load_chunk = [&](int c, int b) {
        int p = c >> 2, kofs = (c & 3) * 64;
        const __nv_bfloat16* SA = (p == 1) ? Alo : Ahi;
        const __nv_bfloat16* SB = (p == 2) ? Blo : Bhi;
        uint32_t baseA = sb + b * 32768;
        uint32_t baseB = baseA + 16384;
        {
            int r = m0 + lrow;
            int v = (r < Meff) ? 16 : 0;
            int rs = (r < Meff) ? r : 0;
            const __nv_bfloat16* ap = SA + (size_t)rs * DIM + kofs + lhalf * 32;
#pragma unroll
            for (int i = 0; i < 4; i++) {
                uint32_t off = (uint32_t)lrow * 128 + lhalf * 64 + i * 16;
                cp_async16(baseA + SWZ(off), ap + i * 8, v);
            }
        }
        {
            const __nv_bfloat16* bp = SB + (size_t)(n0 + lrow) * DIM + kofs + lhalf * 32;
#pragma unroll
            for (int i = 0; i < 4; i++) {
                uint32_t off = (uint32_t)lrow * 128 + lhalf * 64 + i * 16;
                cp_async16(baseB + SWZ(off), bp + i * 8, 16);
            }
        }
    };

    float acc[2][8][4];
#pragma unroll
    for (int mt = 0; mt < 2; mt++)
#pragma unroll
        for (int nt = 0; nt < 8; nt++)
#pragma unroll
            for (int e = 0; e < 4; e++) acc[mt][nt][e] = 0.f;

    load_chunk(0, 0);
    cp_commit();

    for (int c = 0; c < 12; c++) {
        cp_wait0();
        __syncthreads();
        if (c + 1 < 12) { load_chunk(c + 1, (c + 1) & 1); cp_commit(); }

        uint32_t baseA = sb + (c & 1) * 32768;
        uint32_t baseB = baseA + 16384;
        int lr16 = lane & 15;
        int lk = (lane >> 4) * 16;

#pragma unroll
        for (int ks = 0; ks < 4; ks++) {
            int kb = ks * 32 + lk;
            uint32_t a[2][4];
#pragma unroll
            for (int mt = 0; mt < 2; mt++) {
                uint32_t off = (uint32_t)(warp_m * 32 + mt * 16 + lr16) * 128 + kb;
                ldsm_x4(a[mt][0], a[mt][1], a[mt][2], a[mt][3], baseA + SWZ(off));
            }
            uint32_t bfr[4][4];
#pragma unroll
            for (int ng = 0; ng < 4; ng++) {
                uint32_t off = (uint32_t)(warp_n * 64 + ng * 16 + lr16) * 128 + kb;
                ldsm_x4(bfr[ng][0], bfr[ng][1], bfr[ng][2], bfr[ng][3], baseB + SWZ(off));
            }
#pragma unroll
            for (int mt = 0; mt < 2; mt++)
#pragma unroll
                for (int ng = 0; ng < 4; ng++) {
                    mma_bf16(acc[mt][2 * ng],     a[mt], bfr[ng][0], bfr[ng][2]);
                    mma_bf16(acc[mt][2 * ng + 1], a[mt], bfr[ng][1], bfr[ng][3]);
                }
        }
    }

    int gr = lane >> 2, gc = (lane & 3) * 2;
#pragma unroll
    for (int mt = 0; mt < 2; mt++) {
#pragma unroll
        for (int nt = 0; nt < 8; nt++) {
            int col = n0 + warp_n * 64 + nt * 8 + gc;
            float b0 = bias[col], b1 = bias[col + 1];
            int r0 = m0 + warp_m * 32 + mt * 16 + gr;
            int r1 = r0 + 8;
            if (r0 < Meff) {
                float2 v;
                v.x = acc[mt][nt][0] + b0;
                v.y = acc[mt][nt][1] + b1;
                if (RELU) { v.x = fmaxf(v.x, 0.f); v.y = fmaxf(v.y, 0.f); }
                *(float2*)(C + (size_t)r0 * N + col) = v;
            }
            if (r1 < Meff) {
                float2 v;
                v.x = acc[mt][nt][2] + b0;
                v.y = acc[mt][nt][3] + b1;
                if (RELU) { v.x = fmaxf(v.x, 0.f); v.y = fmaxf(v.y, 0.f); }
                *(float2*)(C + (size_t)r1 * N + col) = v;
            }
        }
    }
}

// ---------------- scatter-mean gather -> compact bf16 hi/lo profile rows ----------------
__global__ void k_profile() {
    int w = (blockIdx.x * blockDim.x + threadIdx.x) >> 5;
    int lane = threadIdx.x & 31;
    if (w >= g_nm) return;
    int o = g_list[w];
    int beg = g_off[o];
    int c = g_cnt[o];
    float s[8] = {0, 0, 0, 0, 0, 0, 0, 0};
    const float4* Y4 = (const float4*)g_Y;
    for (int i = 0; i < c; i++) {
        int e = g_sortedEvt[beg + i];
        float4 a = Y4[(size_t)e * 64 + lane * 2];
        float4 b = Y4[(size_t)e * 64 + lane * 2 + 1];
        s[0] += a.x; s[1] += a.y; s[2] += a.z; s[3] += a.w;
        s[4] += b.x; s[5] += b.y; s[6] += b.z; s[7] += b.w;
    }
    float inv = 1.f / fmaxf((float)c, 1.f);
    uint4 hv, lv;
    split2(s[0] * inv, s[1] * inv, hv.x, lv.x);
    split2(s[2] * inv, s[3] * inv, hv.y, lv.y);
    split2(s[4] * inv, s[5] * inv, hv.z, lv.z);
    split2(s[6] * inv, s[7] * inv, hv.w, lv.w);
    ((uint4*)g_Phi)[(size_t)w * 32 + lane] = hv;
    ((uint4*)g_Plo)[(size_t)w * 32 + lane] = lv;
}

// gather objX rows for masked objects -> compact bf16 hi/lo
__global__ void k_convO(const float* __restrict__ objX) {
    int idx = blockIdx.x * blockDim.x + threadIdx.x;
    int r = idx >> 5, lane = idx & 31;
    if (r >= g_nm) return;
    int o = g_list[r];
    float4 a = ((const float4*)objX)[(size_t)o * 64 + lane * 2];
    float4 b = ((const float4*)objX)[(size_t)o * 64 + lane * 2 + 1];
    uint4 hv, lv;
    split2(a.x, a.y, hv.x, lv.x);
    split2(a.z, a.w, hv.y, lv.y);
    split2(b.x, b.y, hv.z, lv.z);
    split2(b.z, b.w, hv.w, lv.w);
    ((uint4*)g_Ohi)[(size_t)r * 32 + lane] = hv;
    ((uint4*)g_Olo)[(size_t)r * 32 + lane] = lv;
}

__global__ void k_copy(const float* __restrict__ X, float* __restrict__ out, int n4) {
    int i = blockIdx.x * blockDim.x + threadIdx.x;
    if (i < n4) ((float4*)out)[i] = ((const float4*)X)[i];
}

__global__ void k_gru(const float* __restrict__ objX, float* __restrict__ out) {
    int r = blockIdx.x;
    if (r >= g_nm) return;
    int c = threadIdx.x;  // 256
    int o = g_list[r];
    float h = objX[(size_t)o * DIM + c];
    const float* gi = g_GI + (size_t)r * 768;
    const float* gh = g_GH + (size_t)r * 768;
    float ir = gi[c], iz = gi[c + 256], in_ = gi[c + 512];
    float hr = gh[c], hz = gh[c + 256], hn = gh[c + 512];
    float rg = 1.f / (1.f + __expf(-(ir + hr)));
    float z  = 1.f / (1.f + __expf(-(iz + hz)));
    float n  = tanhf(in_ + rg * hn);
    out[(size_t)o * DIM + c] = (1.f - z) * n + z * h;
}

// ---------------- launch ----------------
extern "C" void kernel_launch(void* const* d_in, const int* in_sizes, int n_in,
                              void* d_out, int out_size) {
    const float* objX  = (const float*)d_in[0];
    const float* evtX  = (const float*)d_in[1];
    const int*   obj_i = (const int*)d_in[2];
    const int*   evt_i = (const int*)d_in[3];
    const int*   m_idx = (const int*)d_in[4];
    const float* Wp    = (const float*)d_in[5];
    const float* bp    = (const float*)d_in[6];
    const float* Wih   = (const float*)d_in[7];
    const float* bih   = (const float*)d_in[8];
    const float* Whh   = (const float*)d_in[9];
    const float* bhh   = (const float*)d_in[10];
    float* out = (float*)d_out;

    int n_obj  = in_sizes[0] / DIM;
    int n_evt  = in_sizes[1] / DIM;
    int n_edge = in_sizes[2];
    int n_main = in_sizes[4];
    int worstM = (n_main < n_obj) ? n_main : n_obj;

    __nv_bfloat16 *pEhi, *pElo, *pPhi, *pPlo, *pOhi, *pOlo;
    __nv_bfloat16 *pWphi, *pWplo, *pWihHi, *pWihLo, *pWhhHi, *pWhhLo;
    float *pY, *pGI, *pGH;
    int *pNM;
    cudaGetSymbolAddress((void**)&pEhi, g_Ehi);
    cudaGetSymbolAddress((void**)&pElo, g_Elo);
    cudaGetSymbolAddress((void**)&pPhi, g_Phi);
    cudaGetSymbolAddress((void**)&pPlo, g_Plo);
    cudaGetSymbolAddress((void**)&pOhi, g_Ohi);
    cudaGetSymbolAddress((void**)&pOlo, g_Olo);
    cudaGetSymbolAddress((void**)&pWphi, g_Wphi);
    cudaGetSymbolAddress((void**)&pWplo, g_Wplo);
    cudaGetSymbolAddress((void**)&pWihHi, g_WihHi);
    cudaGetSymbolAddress((void**)&pWihLo, g_WihLo);
    cudaGetSymbolAddress((void**)&pWhhHi, g_WhhHi);
    cudaGetSymbolAddress((void**)&pWhhLo, g_WhhLo);
    cudaGetSymbolAddress((void**)&pY, g_Y);
    cudaGetSymbolAddress((void**)&pGI, g_GI);
    cudaGetSymbolAddress((void**)&pGH, g_GH);
    cudaGetSymbolAddress((void**)&pNM, g_nm);

    const int SMEM_BYTES = 2 * 32768;
    cudaFuncSetAttribute(k_tc<0>, cudaFuncAttributeMaxDynamicSharedMemorySize, SMEM_BYTES);
    cudaFuncSetAttribute(k_tc<1>, cudaFuncAttributeMaxDynamicSharedMemorySize, SMEM_BYTES);

    k_zero<<<(n_obj + 255) / 256, 256>>>(n_obj);
    k_split<<<(n_evt * DIM / 8 + 255) / 256, 256>>>(evtX, pEhi, pElo, n_evt * DIM / 8);
    k_split<<<(DIM * DIM / 8 + 255) / 256, 256>>>(Wp, pWphi, pWplo, DIM * DIM / 8);
    k_split<<<(768 * DIM / 8 + 255) / 256, 256>>>(Wih, pWihHi, pWihLo, 768 * DIM / 8);
    k_split<<<(768 * DIM / 8 + 255) / 256, 256>>>(Whh, pWhhHi, pWhhLo, 768 * DIM / 8);

    {
        dim3 g(DIM / 128, (n_evt + 127) / 128);
        k_tc<1><<<g, 256, SMEM_BYTES>>>(pEhi, pElo, pWphi, pWplo, bp, pY,
                                        n_evt, nullptr, DIM);
    }

    k_count<<<(n_edge + 255) / 256, 256>>>(obj_i, n_edge);
    int nb = (n_obj + 1023) / 1024;
    k_scan1<<<nb, 1024>>>(n_obj);
    k_scan2<<<1, 32>>>(nb);
    k_scan3<<<(n_obj + 255) / 256, 256>>>(n_obj);
    k_fill<<<(n_edge + 255) / 256, 256>>>(obj_i, evt_i, n_edge);

    k_list<<<(n_main + 255) / 256, 256>>>(m_idx, n_main);

    k_profile<<<(worstM * 32 + 255) / 256, 256>>>();
    k_convO<<<(worstM * 32 + 255) / 256, 256>>>(objX);

    {
        dim3 g(768 / 128, (worstM + 127) / 128);
        k_tc<0><<<g, 256, SMEM_BYTES>>>(pPhi, pPlo, pWihHi, pWihLo, bih, pGI,
                                        worstM, pNM, 768);
        k_tc<0><<<g, 256, SMEM_BYTES>>>(pOhi, pOlo, pWhhHi, pWhhLo, bhh, pGH,
                                        worstM, pNM, 768);
    }

    k_copy<<<(n_obj * (DIM / 4) + 255) / 256, 256>>>(objX, out, n_obj * (DIM / 4));
    k_gru<<<worstM, DIM>>>(objX, out);
}

// round 9
// speedup vs baseline: 2.9170x; 1.2751x over previous
#include <cuda_runtime.h>
#include <cuda_fp16.h>
#include <cstdint>

#define NOBJ_MAX 50000
#define NEVT_MAX 100000
#define NEDGE_MAX 500000
#define DIM 256

// ---------------- static scratch ----------------
__device__ __align__(16) __half g_Ehi[NEVT_MAX * DIM];
__device__ __align__(16) __half g_Elo[NEVT_MAX * DIM];
__device__ __align__(16) float  g_Y[NEVT_MAX * DIM];
__device__ __align__(16) __half g_Phi[NOBJ_MAX * DIM];
__device__ __align__(16) __half g_Plo[NOBJ_MAX * DIM];
__device__ __align__(16) __half g_Ohi[NOBJ_MAX * DIM];
__device__ __align__(16) __half g_Olo[NOBJ_MAX * DIM];
__device__ __align__(16) __half g_Wp16[DIM * DIM];
__device__ __align__(16) __half g_Wih16[768 * DIM];
__device__ __align__(16) __half g_Whh16[768 * DIM];
__device__ __align__(16) float g_GI[NOBJ_MAX * 768];
__device__ __align__(16) float g_GH[NOBJ_MAX * 768];
__device__ int g_cnt[NOBJ_MAX];
__device__ int g_off[NOBJ_MAX];
__device__ int g_cur[NOBJ_MAX];
__device__ int g_mask[NOBJ_MAX];
__device__ int g_list[NOBJ_MAX];
__device__ int g_sortedEvt[NEDGE_MAX];
__device__ int g_bsum[64];
__device__ int g_nm;

// ---------------- PTX helpers (sm_80-portable only) ----------------
__device__ __forceinline__ uint32_t smem_to_u32(const void* p) {
    uint32_t a;
    asm("{ .reg .u64 t; cvta.to.shared.u64 t, %1; cvt.u32.u64 %0, t; }"
        : "=r"(a) : "l"(p));
    return a;
}
__device__ __forceinline__ void cp_async16(uint32_t dst, const void* src, int src_bytes) {
    asm volatile("cp.async.cg.shared.global [%0], [%1], 16, %2;"
                 :: "r"(dst), "l"(src), "r"(src_bytes) : "memory");
}
__device__ __forceinline__ void cp_commit() {
    asm volatile("cp.async.commit_group;" ::: "memory");
}
__device__ __forceinline__ void cp_wait0() {
    asm volatile("cp.async.wait_group 0;" ::: "memory");
}
__device__ __forceinline__ void ldsm_x4(uint32_t& r0, uint32_t& r1, uint32_t& r2, uint32_t& r3,
                                        uint32_t addr) {
    asm volatile("ldmatrix.sync.aligned.m8n8.x4.shared.b16 {%0,%1,%2,%3}, [%4];"
                 : "=r"(r0), "=r"(r1), "=r"(r2), "=r"(r3) : "r"(addr));
}
__device__ __forceinline__ void mma_f16(float* d, const uint32_t* a,
                                        uint32_t b0, uint32_t b1) {
    asm volatile("mma.sync.aligned.m16n8k16.row.col.f32.f16.f16.f32 "
                 "{%0,%1,%2,%3}, {%4,%5,%6,%7}, {%8,%9}, {%0,%1,%2,%3};"
                 : "+f"(d[0]), "+f"(d[1]), "+f"(d[2]), "+f"(d[3])
                 : "r"(a[0]), "r"(a[1]), "r"(a[2]), "r"(a[3]), "r"(b0), "r"(b1));
}

#define SWZ(o) ((o) ^ (((o) >> 3) & 0x70))

// ---------------- fp16 hi/lo split helpers ----------------
__device__ __forceinline__ uint32_t h2u(__half2 h) {
    union { __half2 h; uint32_t u; } cv; cv.h = h; return cv.u;
}
__device__ __forceinline__ void split2h(float x, float y, uint32_t& h, uint32_t& l) {
    __half2 hh = __floats2half2_rn(x, y);
    float lx = x - __half2float(__low2half(hh));
    float ly = y - __half2float(__high2half(hh));
    h = h2u(hh);
    l = h2u(__floats2half2_rn(lx, ly));
}

// ---------------- small utility kernels ----------------
__global__ void k_zero(int n_obj) {
    int i = blockIdx.x * blockDim.x + threadIdx.x;
    if (i < n_obj) { g_cnt[i] = 0; g_cur[i] = 0; g_mask[i] = 0; }
    if (i == 0) g_nm = 0;
}
__global__ void k_count(const int* __restrict__ obj, int n) {
    int i = blockIdx.x * blockDim.x + threadIdx.x;
    if (i < n) atomicAdd(&g_cnt[obj[i]], 1);
}
__global__ void k_scan1(int n) {
    __shared__ int s[1024];
    int t = threadIdx.x;
    int i = blockIdx.x * 1024 + t;
    int v = (i < n) ? g_cnt[i] : 0;
    s[t] = v; __syncthreads();
    for (int d = 1; d < 1024; d <<= 1) {
        int x = (t >= d) ? s[t - d] : 0;
        __syncthreads();
        s[t] += x;
        __syncthreads();
    }
    if (i < n) g_off[i] = s[t] - v;
    if (t == 1023) g_bsum[blockIdx.x] = s[1023];
}
__global__ void k_scan2(int nb) {
    if (threadIdx.x == 0 && blockIdx.x == 0) {
        int run = 0;
        for (int b = 0; b < nb; b++) { int t = g_bsum[b]; g_bsum[b] = run; run += t; }
    }
}
__global__ void k_scan3(int n) {
    int i = blockIdx.x * blockDim.x + threadIdx.x;
    if (i < n) g_off[i] += g_bsum[i >> 10];
}
__global__ void k_fill(const int* __restrict__ obj, const int* __restrict__ evt, int n) {
    int i = blockIdx.x * blockDim.x + threadIdx.x;
    if (i < n) {
        int o = obj[i];
        int p = atomicAdd(&g_cur[o], 1);
        g_sortedEvt[g_off[o] + p] = evt[i];
    }
}
__global__ void k_list(const int* __restrict__ midx, int n) {
    int i = blockIdx.x * blockDim.x + threadIdx.x;
    if (i < n) {
        int o = midx[i];
        if (atomicExch(&g_mask[o], 1) == 0) {
            int p = atomicAdd(&g_nm, 1);
            g_list[p] = o;
        }
    }
}

// fp32 -> fp16 hi/lo elementwise (8 floats per thread)
__global__ void k_split(const float* __restrict__ x, __half* __restrict__ hi,
                        __half* __restrict__ lo, int n8) {
    int i = blockIdx.x * blockDim.x + threadIdx.x;
    if (i >= n8) return;
    float4 a = ((const float4*)x)[2 * i];
    float4 b = ((const float4*)x)[2 * i + 1];
    uint4 hv, lv;
    split2h(a.x, a.y, hv.x, lv.x);
    split2h(a.z, a.w, hv.y, lv.y);
    split2h(b.x, b.y, hv.z, lv.z);
    split2h(b.z, b.w, hv.w, lv.w);
    ((uint4*)hi)[i] = hv;
    ((uint4*)lo)[i] = lv;
}

// fp32 -> fp16 single (weights / B operand), 8 floats per thread
__global__ void k_cvt16(const float* __restrict__ x, __half* __restrict__ h, int n8) {
    int i = blockIdx.x * blockDim.x + threadIdx.x;
    if (i >= n8) return;
    float4 a = ((const float4*)x)[2 * i];
    float4 b = ((const float4*)x)[2 * i + 1];
    uint4 hv;
    hv.x = h2u(__floats2half2_rn(a.x, a.y));
    hv.y = h2u(__floats2half2_rn(a.z, a.w));
    hv.z = h2u(__floats2half2_rn(b.x, b.y));
    hv.w = h2u(__floats2half2_rn(b.z, b.w));
    ((uint4*)h)[i] = hv;
}

// ---------------- mma.sync split-fp16 GEMM: C = A @ B^T + bias ----------------
// A: [M,256] fp16 hi/lo; B: [N,256] fp16; C: [M,N] fp32.
// Block tile 128x128, K-chunk 64 (128B SW128 rows), 8 chunks = 2 passes
// (hi*B, lo*B) x 4. cp.async double buffer, 1 syncthreads/chunk.
// 8 warps: warp_m = wid&3 (32 rows), warp_n = wid>>2 (64 cols), warp tile 32x64.
template <int RELU>
__global__ __launch_bounds__(256) void k_tc(
    const __half* __restrict__ Ahi, const __half* __restrict__ Alo,
    const __half* __restrict__ B,
    const float* __restrict__ bias, float* __restrict__ C,
    int M, const int* __restrict__ dM, int N)
{
    extern __shared__ __align__(1024) char dsm[];  // 2 x (16KB A + 16KB B)
    int Meff = dM ? *dM : M;
    int m0 = blockIdx.y * 128;
    if (m0 >= Meff) return;
    int n0 = blockIdx.x * 128;

    int tid = threadIdx.x, wid = tid >> 5, lane = tid & 31;
    int warp_m = wid & 3, warp_n = wid >> 2;
    uint32_t sb = smem_to_u32(dsm);

    int lrow = tid >> 1;   // 0..127
    int lhalf = tid & 1;   // 64B half of the 128B row

    auto load_chunk = [&](int c, int b) {
        int p = c >> 2, kofs = (c & 3) * 64;
        const __half* SA = p ? Alo : Ahi;
        uint32_t baseA = sb + b * 32768;
        uint32_t baseB = baseA + 16384;
        {
            int r = m0 + lrow;
            int v = (r < Meff) ? 16 : 0;
            int rs = (r < Meff) ? r : 0;
            const __half* ap = SA + (size_t)rs * DIM + kofs + lhalf * 32;
#pragma unroll
            for (int i = 0; i < 4; i++) {
                uint32_t off = (uint32_t)lrow * 128 + lhalf * 64 + i * 16;
                cp_async16(baseA + SWZ(off), ap + i * 8, v);
            }
        }
        {
            const __half* bp = B + (size_t)(n0 + lrow) * DIM + kofs + lhalf * 32;
#pragma unroll
            for (int i = 0; i < 4; i++) {
                uint32_t off = (uint32_t)lrow * 128 + lhalf * 64 + i * 16;
                cp_async16(baseB + SWZ(off), bp + i * 8, 16);
            }
        }
    };

    float acc[2][8][4];
#pragma unroll
    for (int mt = 0; mt < 2; mt++)
#pragma unroll
        for (int nt = 0; nt < 8; nt++)
#pragma unroll
            for (int e = 0; e < 4; e++) acc[mt][nt][e] = 0.f;

    load_chunk(0, 0);
    cp_commit();

    for (int c = 0; c < 8; c++) {
        cp_wait0();
        __syncthreads();
        if (c + 1 < 8) { load_chunk(c + 1, (c + 1) & 1); cp_commit(); }

        uint32_t baseA = sb + (c & 1) * 32768;
        uint32_t baseB = baseA + 16384;
        int lr16 = lane & 15;
        int lk = (lane >> 4) * 16;

#pragma unroll
        for (int ks = 0; ks < 4; ks++) {
            int kb = ks * 32 + lk;
            uint32_t a[2][4];
#pragma unroll
            for (int mt = 0; mt < 2; mt++) {
                uint32_t off = (uint32_t)(warp_m * 32 + mt * 16 + lr16) * 128 + kb;
                ldsm_x4(a[mt][0], a[mt][1], a[mt][2], a[mt][3], baseA + SWZ(off));
            }
            uint32_t bfr[4][4];
#pragma unroll
            for (int ng = 0; ng < 4; ng++) {
                uint32_t off = (uint32_t)(warp_n * 64 + ng * 16 + lr16) * 128 + kb;
                ldsm_x4(bfr[ng][0], bfr[ng][1], bfr[ng][2], bfr[ng][3], baseB + SWZ(off));
            }
#pragma unroll
            for (int mt = 0; mt < 2; mt++)
#pragma unroll
                for (int ng = 0; ng < 4; ng++) {
                    mma_f16(acc[mt][2 * ng],     a[mt], bfr[ng][0], bfr[ng][2]);
                    mma_f16(acc[mt][2 * ng + 1], a[mt], bfr[ng][1], bfr[ng][3]);
                }
        }
    }

    int gr = lane >> 2, gc = (lane & 3) * 2;
#pragma unroll
    for (int mt = 0; mt < 2; mt++) {
#pragma unroll
        for (int nt = 0; nt < 8; nt++) {
            int col = n0 + warp_n * 64 + nt * 8 + gc;
            float b0 = bias[col], b1 = bias[col + 1];
            int r0 = m0 + warp_m * 32 + mt * 16 + gr;
            int r1 = r0 + 8;
            if (r0 < Meff) {
                float2 v;
                v.x = acc[mt][nt][0] + b0;
                v.y = acc[mt][nt][1] + b1;
                if (RELU) { v.x = fmaxf(v.x, 0.f); v.y = fmaxf(v.y, 0.f); }
                *(float2*)(C + (size_t)r0 * N + col) = v;
            }
            if (r1 < Meff) {
                float2 v;
                v.x = acc[mt][nt][2] + b0;
                v.y = acc[mt][nt][3] + b1;
                if (RELU) { v.x = fmaxf(v.x, 0.f); v.y = fmaxf(v.y, 0.f); }
                *(float2*)(C + (size_t)r1 * N + col) = v;
            }
        }
    }
}

// ---------------- scatter-mean gather -> compact fp16 hi/lo profile rows ----------------
__global__ void k_profile() {
    int w = (blockIdx.x * blockDim.x + threadIdx.x) >> 5;
    int lane = threadIdx.x & 31;
    if (w >= g_nm) return;
    int o = g_list[w];
    int beg = g_off[o];
    int c = g_cnt[o];
    float s[8] = {0, 0, 0, 0, 0, 0, 0, 0};
    const float4* Y4 = (const float4*)g_Y;
    for (int i = 0; i < c; i++) {
        int e = g_sortedEvt[beg + i];
        float4 a = Y4[(size_t)e * 64 + lane * 2];
        float4 b = Y4[(size_t)e * 64 + lane * 2 + 1];
        s[0] += a.x; s[1] += a.y; s[2] += a.z; s[3] += a.w;
        s[4] += b.x; s[5] += b.y; s[6] += b.z; s[7] += b.w;
    }
    float inv = 1.f / fmaxf((float)c, 1.f);
    uint4 hv, lv;
    split2h(s[0] * inv, s[1] * inv, hv.x, lv.x);
    split2h(s[2] * inv, s[3] * inv, hv.y, lv.y);
    split2h(s[4] * inv, s[5] * inv, hv.z, lv.z);
    split2h(s[6] * inv, s[7] * inv, hv.w, lv.w);
    ((uint4*)g_Phi)[(size_t)w * 32 + lane] = hv;
    ((uint4*)g_Plo)[(size_t)w * 32 + lane] = lv;
}

// gather objX rows for masked objects -> compact fp16 hi/lo
__global__ void k_convO(const float* __restrict__ objX) {
    int idx = blockIdx.x * blockDim.x + threadIdx.x;
    int r = idx >> 5, lane = idx & 31;
    if (r >= g_nm) return;
    int o = g_list[r];
    float4 a = ((const float4*)objX)[(size_t)o * 64 + lane * 2];
    float4 b = ((const float4*)objX)[(size_t)o * 64 + lane * 2 + 1];
    uint4 hv, lv;
    split2h(a.x, a.y, hv.x, lv.x);
    split2h(a.z, a.w, hv.y, lv.y);
    split2h(b.x, b.y, hv.z, lv.z);
    split2h(b.z, b.w, hv.w, lv.w);
    ((uint4*)g_Ohi)[(size_t)r * 32 + lane] = hv;
    ((uint4*)g_Olo)[(size_t)r * 32 + lane] = lv;
}

__global__ void k_copy(const float* __restrict__ X, float* __restrict__ out, int n4) {
    int i = blockIdx.x * blockDim.x + threadIdx.x;
    if (i < n4) ((float4*)out)[i] = ((const float4*)X)[i];
}

__global__ void k_gru(const float* __restrict__ objX, float* __restrict__ out) {
    int r = blockIdx.x;
    if (r >= g_nm) return;
    int c = threadIdx.x;  // 256
    int o = g_list[r];
    float h = objX[(size_t)o * DIM + c];
    const float* gi = g_GI + (size_t)r * 768;
    const float* gh = g_GH + (size_t)r * 768;
    float ir = gi[c], iz = gi[c + 256], in_ = gi[c + 512];
    float hr = gh[c], hz = gh[c + 256], hn = gh[c + 512];
    float rg = 1.f / (1.f + __expf(-(ir + hr)));
    float z  = 1.f / (1.f + __expf(-(iz + hz)));
    float n  = tanhf(in_ + rg * hn);
    out[(size_t)o * DIM + c] = (1.f - z) * n + z * h;
}

// ---------------- launch ----------------
extern "C" void kernel_launch(void* const* d_in, const int* in_sizes, int n_in,
                              void* d_out, int out_size) {
    const float* objX  = (const float*)d_in[0];
    const float* evtX  = (const float*)d_in[1];
    const int*   obj_i = (const int*)d_in[2];
    const int*   evt_i = (const int*)d_in[3];
    const int*   m_idx = (const int*)d_in[4];
    const float* Wp    = (const float*)d_in[5];
    const float* bp    = (const float*)d_in[6];
    const float* Wih   = (const float*)d_in[7];
    const float* bih   = (const float*)d_in[8];
    const float* Whh   = (const float*)d_in[9];
    const float* bhh   = (const float*)d_in[10];
    float* out = (float*)d_out;

    int n_obj  = in_sizes[0] / DIM;
    int n_evt  = in_sizes[1] / DIM;
    int n_edge = in_sizes[2];
    int n_main = in_sizes[4];
    int worstM = (n_main < n_obj) ? n_main : n_obj;

    __half *pEhi, *pElo, *pPhi, *pPlo, *pOhi, *pOlo;
    __half *pWp16, *pWih16, *pWhh16;
    float *pY, *pGI, *pGH;
    int *pNM;
    cudaGetSymbolAddress((void**)&pEhi, g_Ehi);
    cudaGetSymbolAddress((void**)&pElo, g_Elo);
    cudaGetSymbolAddress((void**)&pPhi, g_Phi);
    cudaGetSymbolAddress((void**)&pPlo, g_Plo);
    cudaGetSymbolAddress((void**)&pOhi, g_Ohi);
    cudaGetSymbolAddress((void**)&pOlo, g_Olo);
    cudaGetSymbolAddress((void**)&pWp16, g_Wp16);
    cudaGetSymbolAddress((void**)&pWih16, g_Wih16);
    cudaGetSymbolAddress((void**)&pWhh16, g_Whh16);
    cudaGetSymbolAddress((void**)&pY, g_Y);
    cudaGetSymbolAddress((void**)&pGI, g_GI);
    cudaGetSymbolAddress((void**)&pGH, g_GH);
    cudaGetSymbolAddress((void**)&pNM, g_nm);

    const int SMEM_BYTES = 2 * 32768;
    cudaFuncSetAttribute(k_tc<0>, cudaFuncAttributeMaxDynamicSharedMemorySize, SMEM_BYTES);
    cudaFuncSetAttribute(k_tc<1>, cudaFuncAttributeMaxDynamicSharedMemorySize, SMEM_BYTES);

    // 1. bookkeeping + conversions
    k_zero<<<(n_obj + 255) / 256, 256>>>(n_obj);
    k_split<<<(n_evt * DIM / 8 + 255) / 256, 256>>>(evtX, pEhi, pElo, n_evt * DIM / 8);
    k_cvt16<<<(DIM * DIM / 8 + 255) / 256, 256>>>(Wp, pWp16, DIM * DIM / 8);
    k_cvt16<<<(768 * DIM / 8 + 255) / 256, 256>>>(Wih, pWih16, 768 * DIM / 8);
    k_cvt16<<<(768 * DIM / 8 + 255) / 256, 256>>>(Whh, pWhh16, 768 * DIM / 8);

    // 2. Y = relu(event_X @ Wp^T + bp)
    {
        dim3 g(DIM / 128, (n_evt + 127) / 128);
        k_tc<1><<<g, 256, SMEM_BYTES>>>(pEhi, pElo, pWp16, bp, pY,
                                        n_evt, nullptr, DIM);
    }

    // 3. CSR build
    k_count<<<(n_edge + 255) / 256, 256>>>(obj_i, n_edge);
    int nb = (n_obj + 1023) / 1024;
    k_scan1<<<nb, 1024>>>(n_obj);
    k_scan2<<<1, 32>>>(nb);
    k_scan3<<<(n_obj + 255) / 256, 256>>>(n_obj);
    k_fill<<<(n_edge + 255) / 256, 256>>>(obj_i, evt_i, n_edge);

    // 4. compact unique masked objects
    k_list<<<(n_main + 255) / 256, 256>>>(m_idx, n_main);

    // 5. scatter-mean gather + objX gather (compact fp16 hi/lo)
    k_profile<<<(worstM * 32 + 255) / 256, 256>>>();
    k_convO<<<(worstM * 32 + 255) / 256, 256>>>(objX);

    // 6. GRU GEMMs over compact rows
    {
        dim3 g(768 / 128, (worstM + 127) / 128);
        k_tc<0><<<g, 256, SMEM_BYTES>>>(pPhi, pPlo, pWih16, bih, pGI,
                                        worstM, pNM, 768);
        k_tc<0><<<g, 256, SMEM_BYTES>>>(pOhi, pOlo, pWhh16, bhh, pGH,
                                        worstM, pNM, 768);
    }

    // 7. pass-through copy, then masked GRU overwrite
    k_copy<<<(n_obj * (DIM / 4) + 255) / 256, 256>>>(objX, out, n_obj * (DIM / 4));
    k_gru<<<worstM, DIM>>>(objX, out);
}

// round 10
// speedup vs baseline: 5.9607x; 2.0434x over previous
#include <cuda_runtime.h>
#include <cuda_fp16.h>
#include <cstdint>

#define NOBJ_MAX 50000
#define NEVT_MAX 100000
#define NEDGE_MAX 500000
#define DIM 256

// ---------------- static scratch ----------------
__device__ __align__(16) __half g_E16[NEVT_MAX * DIM];   // event_X fp16
__device__ __align__(16) __half g_Y[NEVT_MAX * DIM];     // relu(event_X @ Wp^T + bp), fp16
__device__ __align__(16) __half g_P16[NOBJ_MAX * DIM];   // compact profile rows fp16
__device__ __align__(16) __half g_O16[NOBJ_MAX * DIM];   // compact objX rows fp16
__device__ __align__(16) __half g_Wp16[DIM * DIM];
__device__ __align__(16) __half g_Wih16[768 * DIM];
__device__ __align__(16) __half g_Whh16[768 * DIM];
__device__ __align__(16) float g_GI[NOBJ_MAX * 768];
__device__ __align__(16) float g_GH[NOBJ_MAX * 768];
__device__ int g_cnt[NOBJ_MAX];
__device__ int g_off[NOBJ_MAX];
__device__ int g_cur[NOBJ_MAX];
__device__ int g_mask[NOBJ_MAX];
__device__ int g_list[NOBJ_MAX];
__device__ int g_sortedEvt[NEDGE_MAX];
__device__ int g_bsum[64];
__device__ int g_nm;

// ---------------- PTX helpers (sm_80-portable only) ----------------
__device__ __forceinline__ uint32_t smem_to_u32(const void* p) {
    uint32_t a;
    asm("{ .reg .u64 t; cvta.to.shared.u64 t, %1; cvt.u32.u64 %0, t; }"
        : "=r"(a) : "l"(p));
    return a;
}
__device__ __forceinline__ void cp_async16(uint32_t dst, const void* src, int src_bytes) {
    asm volatile("cp.async.cg.shared.global [%0], [%1], 16, %2;"
                 :: "r"(dst), "l"(src), "r"(src_bytes) : "memory");
}
__device__ __forceinline__ void cp_commit() {
    asm volatile("cp.async.commit_group;" ::: "memory");
}
__device__ __forceinline__ void cp_wait0() {
    asm volatile("cp.async.wait_group 0;" ::: "memory");
}
__device__ __forceinline__ void ldsm_x4(uint32_t& r0, uint32_t& r1, uint32_t& r2, uint32_t& r3,
                                        uint32_t addr) {
    asm volatile("ldmatrix.sync.aligned.m8n8.x4.shared.b16 {%0,%1,%2,%3}, [%4];"
                 : "=r"(r0), "=r"(r1), "=r"(r2), "=r"(r3) : "r"(addr));
}
__device__ __forceinline__ void mma_f16(float* d, const uint32_t* a,
                                        uint32_t b0, uint32_t b1) {
    asm volatile("mma.sync.aligned.m16n8k16.row.col.f32.f16.f16.f32 "
                 "{%0,%1,%2,%3}, {%4,%5,%6,%7}, {%8,%9}, {%0,%1,%2,%3};"
                 : "+f"(d[0]), "+f"(d[1]), "+f"(d[2]), "+f"(d[3])
                 : "r"(a[0]), "r"(a[1]), "r"(a[2]), "r"(a[3]), "r"(b0), "r"(b1));
}

#define SWZ(o) ((o) ^ (((o) >> 3) & 0x70))

__device__ __forceinline__ uint32_t h2u(__half2 h) {
    union { __half2 h; uint32_t u; } cv; cv.h = h; return cv.u;
}

// ---------------- small utility kernels ----------------
__global__ void k_zero(int n_obj) {
    int i = blockIdx.x * blockDim.x + threadIdx.x;
    if (i < n_obj) { g_cnt[i] = 0; g_cur[i] = 0; g_mask[i] = 0; }
    if (i == 0) g_nm = 0;
}
__global__ void k_count(const int* __restrict__ obj, int n) {
    int i = blockIdx.x * blockDim.x + threadIdx.x;
    if (i < n) atomicAdd(&g_cnt[obj[i]], 1);
}
__global__ void k_scan1(int n) {
    __shared__ int s[1024];
    int t = threadIdx.x;
    int i = blockIdx.x * 1024 + t;
    int v = (i < n) ? g_cnt[i] : 0;
    s[t] = v; __syncthreads();
    for (int d = 1; d < 1024; d <<= 1) {
        int x = (t >= d) ? s[t - d] : 0;
        __syncthreads();
        s[t] += x;
        __syncthreads();
    }
    if (i < n) g_off[i] = s[t] - v;
    if (t == 1023) g_bsum[blockIdx.x] = s[1023];
}
__global__ void k_scan2(int nb) {
    if (threadIdx.x == 0 && blockIdx.x == 0) {
        int run = 0;
        for (int b = 0; b < nb; b++) { int t = g_bsum[b]; g_bsum[b] = run; run += t; }
    }
}
__global__ void k_scan3(int n) {
    int i = blockIdx.x * blockDim.x + threadIdx.x;
    if (i < n) g_off[i] += g_bsum[i >> 10];
}
__global__ void k_fill(const int* __restrict__ obj, const int* __restrict__ evt, int n) {
    int i = blockIdx.x * blockDim.x + threadIdx.x;
    if (i < n) {
        int o = obj[i];
        int p = atomicAdd(&g_cur[o], 1);
        g_sortedEvt[g_off[o] + p] = evt[i];
    }
}
__global__ void k_list(const int* __restrict__ midx, int n) {
    int i = blockIdx.x * blockDim.x + threadIdx.x;
    if (i < n) {
        int o = midx[i];
        if (atomicExch(&g_mask[o], 1) == 0) {
            int p = atomicAdd(&g_nm, 1);
            g_list[p] = o;
        }
    }
}

// fp32 -> fp16, 8 floats per thread
__global__ void k_cvt16(const float* __restrict__ x, __half* __restrict__ h, int n8) {
    int i = blockIdx.x * blockDim.x + threadIdx.x;
    if (i >= n8) return;
    float4 a = ((const float4*)x)[2 * i];
    float4 b = ((const float4*)x)[2 * i + 1];
    uint4 hv;
    hv.x = h2u(__floats2half2_rn(a.x, a.y));
    hv.y = h2u(__floats2half2_rn(a.z, a.w));
    hv.z = h2u(__floats2half2_rn(b.x, b.y));
    hv.w = h2u(__floats2half2_rn(b.z, b.w));
    ((uint4*)h)[i] = hv;
}

// ---------------- mma.sync fp16 GEMM: C = A @ B^T + bias ----------------
// A: [M,256] fp16; B: [N,256] fp16; C: [M,N] fp32 or fp16 (HOUT).
// Block tile 128x128, K-chunk 64 (128B SW128 rows), 4 chunks.
// cp.async double buffer, 1 syncthreads/chunk.
// 8 warps: warp_m = wid&3 (32 rows), warp_n = wid>>2 (64 cols), warp tile 32x64.
template <int RELU, int HOUT>
__global__ __launch_bounds__(256) void k_tc(
    const __half* __restrict__ A, const __half* __restrict__ B,
    const float* __restrict__ bias, void* __restrict__ Cv,
    int M, const int* __restrict__ dM, int N)
{
    extern __shared__ __align__(1024) char dsm[];  // 2 x (16KB A + 16KB B)
    int Meff = dM ? *dM : M;
    int m0 = blockIdx.y * 128;
    if (m0 >= Meff) return;
    int n0 = blockIdx.x * 128;

    int tid = threadIdx.x, wid = tid >> 5, lane = tid & 31;
    int warp_m = wid & 3, warp_n = wid >> 2;
    uint32_t sb = smem_to_u32(dsm);

    int lrow = tid >> 1;   // 0..127
    int lhalf = tid & 1;   // 64B half of the 128B row

    auto load_chunk = [&](int c, int b) {
        int kofs = c * 64;
        uint32_t baseA = sb + b * 32768;
        uint32_t baseB = baseA + 16384;
        {
            int r = m0 + lrow;
            int v = (r < Meff) ? 16 : 0;
            int rs = (r < Meff) ? r : 0;
            const __half* ap = A + (size_t)rs * DIM + kofs + lhalf * 32;
#pragma unroll
            for (int i = 0; i < 4; i++) {
                uint32_t off = (uint32_t)lrow * 128 + lhalf * 64 + i * 16;
                cp_async16(baseA + SWZ(off), ap + i * 8, v);
            }
        }
        {
            const __half* bp = B + (size_t)(n0 + lrow) * DIM + kofs + lhalf * 32;
#pragma unroll
            for (int i = 0; i < 4; i++) {
                uint32_t off = (uint32_t)lrow * 128 + lhalf * 64 + i * 16;
                cp_async16(baseB + SWZ(off), bp + i * 8, 16);
            }
        }
    };

    float acc[2][8][4];
#pragma unroll
    for (int mt = 0; mt < 2; mt++)
#pragma unroll
        for (int nt = 0; nt < 8; nt++)
#pragma unroll
            for (int e = 0; e < 4; e++) acc[mt][nt][e] = 0.f;

    load_chunk(0, 0);
    cp_commit();

    for (int c = 0; c < 4; c++) {
        cp_wait0();
        __syncthreads();
        if (c + 1 < 4) { load_chunk(c + 1, (c + 1) & 1); cp_commit(); }

        uint32_t baseA = sb + (c & 1) * 32768;
        uint32_t baseB = baseA + 16384;
        int lr16 = lane & 15;
        int lk = (lane >> 4) * 16;

#pragma unroll
        for (int ks = 0; ks < 4; ks++) {
            int kb = ks * 32 + lk;
            uint32_t a[2][4];
#pragma unroll
            for (int mt = 0; mt < 2; mt++) {
                uint32_t off = (uint32_t)(warp_m * 32 + mt * 16 + lr16) * 128 + kb;
                ldsm_x4(a[mt][0], a[mt][1], a[mt][2], a[mt][3], baseA + SWZ(off));
            }
            uint32_t bfr[4][4];
#pragma unroll
            for (int ng = 0; ng < 4; ng++) {
                uint32_t off = (uint32_t)(warp_n * 64 + ng * 16 + lr16) * 128 + kb;
                ldsm_x4(bfr[ng][0], bfr[ng][1], bfr[ng][2], bfr[ng][3], baseB + SWZ(off));
            }
#pragma unroll
            for (int mt = 0; mt < 2; mt++)
#pragma unroll
                for (int ng = 0; ng < 4; ng++) {
                    mma_f16(acc[mt][2 * ng],     a[mt], bfr[ng][0], bfr[ng][2]);
                    mma_f16(acc[mt][2 * ng + 1], a[mt], bfr[ng][1], bfr[ng][3]);
                }
        }
    }

    int gr = lane >> 2, gc = (lane & 3) * 2;
#pragma unroll
    for (int mt = 0; mt < 2; mt++) {
#pragma unroll
        for (int nt = 0; nt < 8; nt++) {
            int col = n0 + warp_n * 64 + nt * 8 + gc;
            float b0 = bias[col], b1 = bias[col + 1];
            int r0 = m0 + warp_m * 32 + mt * 16 + gr;
            int r1 = r0 + 8;
#pragma unroll
            for (int half = 0; half < 2; half++) {
                int r = half ? r1 : r0;
                if (r >= Meff) continue;
                float vx = acc[mt][nt][2 * half + 0] + b0;
                float vy = acc[mt][nt][2 * half + 1] + b1;
                if (RELU) { vx = fmaxf(vx, 0.f); vy = fmaxf(vy, 0.f); }
                if (HOUT) {
                    __half* C = (__half*)Cv;
                    *(__half2*)(C + (size_t)r * N + col) = __floats2half2_rn(vx, vy);
                } else {
                    float* C = (float*)Cv;
                    *(float2*)(C + (size_t)r * N + col) = make_float2(vx, vy);
                }
            }
        }
    }
}

// ---------------- scatter-mean gather (fp16 Y) -> compact fp16 profile rows ----------------
__global__ void k_profile() {
    int w = (blockIdx.x * blockDim.x + threadIdx.x) >> 5;
    int lane = threadIdx.x & 31;
    if (w >= g_nm) return;
    int o = g_list[w];
    int beg = g_off[o];
    int c = g_cnt[o];
    float s[8] = {0, 0, 0, 0, 0, 0, 0, 0};
    const uint4* Y4 = (const uint4*)g_Y;   // 8 halves per lane
    for (int i = 0; i < c; i++) {
        int e = g_sortedEvt[beg + i];
        uint4 v = Y4[(size_t)e * 32 + lane];
        float2 p0 = __half22float2(*(__half2*)&v.x);
        float2 p1 = __half22float2(*(__half2*)&v.y);
        float2 p2 = __half22float2(*(__half2*)&v.z);
        float2 p3 = __half22float2(*(__half2*)&v.w);
        s[0] += p0.x; s[1] += p0.y; s[2] += p1.x; s[3] += p1.y;
        s[4] += p2.x; s[5] += p2.y; s[6] += p3.x; s[7] += p3.y;
    }
    float inv = 1.f / fmaxf((float)c, 1.f);
    uint4 hv;
    hv.x = h2u(__floats2half2_rn(s[0] * inv, s[1] * inv));
    hv.y = h2u(__floats2half2_rn(s[2] * inv, s[3] * inv));
    hv.z = h2u(__floats2half2_rn(s[4] * inv, s[5] * inv));
    hv.w = h2u(__floats2half2_rn(s[6] * inv, s[7] * inv));
    ((uint4*)g_P16)[(size_t)w * 32 + lane] = hv;
}

// gather objX rows for masked objects -> compact fp16
__global__ void k_convO(const float* __restrict__ objX) {
    int idx = blockIdx.x * blockDim.x + threadIdx.x;
    int r = idx >> 5, lane = idx & 31;
    if (r >= g_nm) return;
    int o = g_list[r];
    float4 a = ((const float4*)objX)[(size_t)o * 64 + lane * 2];
    float4 b = ((const float4*)objX)[(size_t)o * 64 + lane * 2 + 1];
    uint4 hv;
    hv.x = h2u(__floats2half2_rn(a.x, a.y));
    hv.y = h2u(__floats2half2_rn(a.z, a.w));
    hv.z = h2u(__floats2half2_rn(b.x, b.y));
    hv.w = h2u(__floats2half2_rn(b.z, b.w));
    ((uint4*)g_O16)[(size_t)r * 32 + lane] = hv;
}

__global__ void k_copy(const float* __restrict__ X, float* __restrict__ out, int n4) {
    int i = blockIdx.x * blockDim.x + threadIdx.x;
    if (i < n4) ((float4*)out)[i] = ((const float4*)X)[i];
}

__global__ void k_gru(const float* __restrict__ objX, float* __restrict__ out) {
    int r = blockIdx.x;
    if (r >= g_nm) return;
    int c = threadIdx.x;  // 256
    int o = g_list[r];
    float h = objX[(size_t)o * DIM + c];
    const float* gi = g_GI + (size_t)r * 768;
    const float* gh = g_GH + (size_t)r * 768;
    float ir = gi[c], iz = gi[c + 256], in_ = gi[c + 512];
    float hr = gh[c], hz = gh[c + 256], hn = gh[c + 512];
    float rg = 1.f / (1.f + __expf(-(ir + hr)));
    float z  = 1.f / (1.f + __expf(-(iz + hz)));
    float n  = tanhf(in_ + rg * hn);
    out[(size_t)o * DIM + c] = (1.f - z) * n + z * h;
}

// ---------------- launch ----------------
extern "C" void kernel_launch(void* const* d_in, const int* in_sizes, int n_in,
                              void* d_out, int out_size) {
    const float* objX  = (const float*)d_in[0];
    const float* evtX  = (const float*)d_in[1];
    const int*   obj_i = (const int*)d_in[2];
    const int*   evt_i = (const int*)d_in[3];
    const int*   m_idx = (const int*)d_in[4];
    const float* Wp    = (const float*)d_in[5];
    const float* bp    = (const float*)d_in[6];
    const float* Wih   = (const float*)d_in[7];
    const float* bih   = (const float*)d_in[8];
    const float* Whh   = (const float*)d_in[9];
    const float* bhh   = (const float*)d_in[10];
    float* out = (float*)d_out;

    int n_obj  = in_sizes[0] / DIM;
    int n_evt  = in_sizes[1] / DIM;
    int n_edge = in_sizes[2];
    int n_main = in_sizes[4];
    int worstM = (n_main < n_obj) ? n_main : n_obj;

    __half *pE16, *pY, *pP16, *pO16, *pWp16, *pWih16, *pWhh16;
    float *pGI, *pGH;
    int *pNM;
    cudaGetSymbolAddress((void**)&pE16, g_E16);
    cudaGetSymbolAddress((void**)&pY, g_Y);
    cudaGetSymbolAddress((void**)&pP16, g_P16);
    cudaGetSymbolAddress((void**)&pO16, g_O16);
    cudaGetSymbolAddress((void**)&pWp16, g_Wp16);
    cudaGetSymbolAddress((void**)&pWih16, g_Wih16);
    cudaGetSymbolAddress((void**)&pWhh16, g_Whh16);
    cudaGetSymbolAddress((void**)&pGI, g_GI);
    cudaGetSymbolAddress((void**)&pGH, g_GH);
    cudaGetSymbolAddress((void**)&pNM, g_nm);

    const int SMEM_BYTES = 2 * 32768;
    cudaFuncSetAttribute(k_tc<0, 0>, cudaFuncAttributeMaxDynamicSharedMemorySize, SMEM_BYTES);
    cudaFuncSetAttribute(k_tc<1, 1>, cudaFuncAttributeMaxDynamicSharedMemorySize, SMEM_BYTES);

    // 1. bookkeeping + fp16 conversions
    k_zero<<<(n_obj + 255) / 256, 256>>>(n_obj);
    k_cvt16<<<(n_evt * DIM / 8 + 255) / 256, 256>>>(evtX, pE16, n_evt * DIM / 8);
    k_cvt16<<<(DIM * DIM / 8 + 255) / 256, 256>>>(Wp, pWp16, DIM * DIM / 8);
    k_cvt16<<<(768 * DIM / 8 + 255) / 256, 256>>>(Wih, pWih16, 768 * DIM / 8);
    k_cvt16<<<(768 * DIM / 8 + 255) / 256, 256>>>(Whh, pWhh16, 768 * DIM / 8);

    // 2. Y = relu(event_X @ Wp^T + bp), fp16 output
    {
        dim3 g(DIM / 128, (n_evt + 127) / 128);
        k_tc<1, 1><<<g, 256, SMEM_BYTES>>>(pE16, pWp16, bp, pY, n_evt, nullptr, DIM);
    }

    // 3. CSR build
    k_count<<<(n_edge + 255) / 256, 256>>>(obj_i, n_edge);
    int nb = (n_obj + 1023) / 1024;
    k_scan1<<<nb, 1024>>>(n_obj);
    k_scan2<<<1, 32>>>(nb);
    k_scan3<<<(n_obj + 255) / 256, 256>>>(n_obj);
    k_fill<<<(n_edge + 255) / 256, 256>>>(obj_i, evt_i, n_edge);

    // 4. compact unique masked objects
    k_list<<<(n_main + 255) / 256, 256>>>(m_idx, n_main);

    // 5. scatter-mean gather + objX gather (compact fp16)
    k_profile<<<(worstM * 32 + 255) / 256, 256>>>();
    k_convO<<<(worstM * 32 + 255) / 256, 256>>>(objX);

    // 6. GRU GEMMs over compact rows (fp32 output)
    {
        dim3 g(768 / 128, (worstM + 127) / 128);
        k_tc<0, 0><<<g, 256, SMEM_BYTES>>>(pP16, pWih16, bih, pGI, worstM, pNM, 768);
        k_tc<0, 0><<<g, 256, SMEM_BYTES>>>(pO16, pWhh16, bhh, pGH, worstM, pNM, 768);
    }

    // 7. pass-through copy, then masked GRU overwrite
    k_copy<<<(n_obj * (DIM / 4) + 255) / 256, 256>>>(objX, out, n_obj * (DIM / 4));
    k_gru<<<worstM, DIM>>>(objX, out);
}

// round 14
// speedup vs baseline: 6.0501x; 1.0150x over previous
#include <cuda_runtime.h>
#include <cuda_fp16.h>
#include <cstdint>

#define NOBJ_MAX 50000
#define NEVT_MAX 100000
#define NEDGE_MAX 500000
#define DIM 256

// ---------------- static scratch ----------------
__device__ __align__(16) __half g_E16[NEVT_MAX * DIM];   // event_X fp16
__device__ __align__(16) __half g_Y[NEVT_MAX * DIM];     // relu(event_X @ Wp^T + bp), fp16
__device__ __align__(16) __half g_P16[NOBJ_MAX * DIM];   // compact profile rows fp16
__device__ __align__(16) __half g_O16[NOBJ_MAX * DIM];   // compact objX rows fp16
__device__ __align__(16) __half g_Wp16[DIM * DIM];
__device__ __align__(16) __half g_Wih16[768 * DIM];
__device__ __align__(16) __half g_Whh16[768 * DIM];
__device__ __align__(16) __half g_GIh[NOBJ_MAX * 768];   // gi gates fp16
__device__ __align__(16) __half g_GHh[NOBJ_MAX * 768];   // gh gates fp16
__device__ int g_cnt[NOBJ_MAX];
__device__ int g_off[NOBJ_MAX];
__device__ int g_cur[NOBJ_MAX];
__device__ int g_mask[NOBJ_MAX];
__device__ int g_list[NOBJ_MAX];
__device__ int g_rowof[NOBJ_MAX];
__device__ int g_sortedEvt[NEDGE_MAX];
__device__ int g_bsum[64];
__device__ int g_nm;

// ---------------- PTX helpers (sm_80-portable only) ----------------
__device__ __forceinline__ uint32_t smem_to_u32(const void* p) {
    uint32_t a;
    asm("{ .reg .u64 t; cvta.to.shared.u64 t, %1; cvt.u32.u64 %0, t; }"
        : "=r"(a) : "l"(p));
    return a;
}
__device__ __forceinline__ void cp_async16(uint32_t dst, const void* src, int src_bytes) {
    asm volatile("cp.async.cg.shared.global [%0], [%1], 16, %2;"
                 :: "r"(dst), "l"(src), "r"(src_bytes) : "memory");
}
__device__ __forceinline__ void cp_commit() {
    asm volatile("cp.async.commit_group;" ::: "memory");
}
__device__ __forceinline__ void cp_wait0() {
    asm volatile("cp.async.wait_group 0;" ::: "memory");
}
__device__ __forceinline__ void cp_wait1() {
    asm volatile("cp.async.wait_group 1;" ::: "memory");
}
__device__ __forceinline__ void ldsm_x4(uint32_t& r0, uint32_t& r1, uint32_t& r2, uint32_t& r3,
                                        uint32_t addr) {
    asm volatile("ldmatrix.sync.aligned.m8n8.x4.shared.b16 {%0,%1,%2,%3}, [%4];"
                 : "=r"(r0), "=r"(r1), "=r"(r2), "=r"(r3) : "r"(addr));
}
__device__ __forceinline__ void mma_f16(float* d, const uint32_t* a,
                                        uint32_t b0, uint32_t b1) {
    asm volatile("mma.sync.aligned.m16n8k16.row.col.f32.f16.f16.f32 "
                 "{%0,%1,%2,%3}, {%4,%5,%6,%7}, {%8,%9}, {%0,%1,%2,%3};"
                 : "+f"(d[0]), "+f"(d[1]), "+f"(d[2]), "+f"(d[3])
                 : "r"(a[0]), "r"(a[1]), "r"(a[2]), "r"(a[3]), "r"(b0), "r"(b1));
}

#define SWZ(o) ((o) ^ (((o) >> 3) & 0x70))

__device__ __forceinline__ uint32_t h2u(__half2 h) {
    union { __half2 h; uint32_t u; } cv; cv.h = h; return cv.u;
}

// ---------------- small utility kernels ----------------
__global__ void k_zero(int n_obj) {
    int i = blockIdx.x * blockDim.x + threadIdx.x;
    if (i < n_obj) { g_cnt[i] = 0; g_cur[i] = 0; g_mask[i] = 0; }
    if (i == 0) g_nm = 0;
}
__global__ void k_count(const int* __restrict__ obj, int n) {
    int i = blockIdx.x * blockDim.x + threadIdx.x;
    if (i < n) atomicAdd(&g_cnt[obj[i]], 1);
}
__global__ void k_scan1(int n) {
    __shared__ int s[1024];
    int t = threadIdx.x;
    int i = blockIdx.x * 1024 + t;
    int v = (i < n) ? g_cnt[i] : 0;
    s[t] = v; __syncthreads();
    for (int d = 1; d < 1024; d <<= 1) {
        int x = (t >= d) ? s[t - d] : 0;
        __syncthreads();
        s[t] += x;
        __syncthreads();
    }
    if (i < n) g_off[i] = s[t] - v;
    if (t == 1023) g_bsum[blockIdx.x] = s[1023];
}
__global__ void k_scan2(int nb) {
    if (threadIdx.x == 0 && blockIdx.x == 0) {
        int run = 0;
        for (int b = 0; b < nb; b++) { int t = g_bsum[b]; g_bsum[b] = run; run += t; }
    }
}
__global__ void k_scan3(int n) {
    int i = blockIdx.x * blockDim.x + threadIdx.x;
    if (i < n) g_off[i] += g_bsum[i >> 10];
}
__global__ void k_fill(const int* __restrict__ obj, const int* __restrict__ evt, int n) {
    int i = blockIdx.x * blockDim.x + threadIdx.x;
    if (i < n) {
        int o = obj[i];
        int p = atomicAdd(&g_cur[o], 1);
        g_sortedEvt[g_off[o] + p] = evt[i];
    }
}
__global__ void k_list(const int* __restrict__ midx, int n) {
    int i = blockIdx.x * blockDim.x + threadIdx.x;
    if (i < n) {
        int o = midx[i];
        if (atomicExch(&g_mask[o], 1) == 0) {
            int p = atomicAdd(&g_nm, 1);
            g_list[p] = o;
            g_rowof[o] = p;
        }
    }
}

// fp32 -> fp16, 8 floats per thread
__global__ void k_cvt16(const float* __restrict__ x, __half* __restrict__ h, int n8) {
    int i = blockIdx.x * blockDim.x + threadIdx.x;
    if (i >= n8) return;
    float4 a = ((const float4*)x)[2 * i];
    float4 b = ((const float4*)x)[2 * i + 1];
    uint4 hv;
    hv.x = h2u(__floats2half2_rn(a.x, a.y));
    hv.y = h2u(__floats2half2_rn(a.z, a.w));
    hv.z = h2u(__floats2half2_rn(b.x, b.y));
    hv.w = h2u(__floats2half2_rn(b.z, b.w));
    ((uint4*)h)[i] = hv;
}

// ---------------- mma.sync fp16 GEMM: C = A @ B^T + bias ----------------
// A: [M,256] fp16; B: [N,256] fp16; C: [M,N] fp32 or fp16 (HOUT).
// Block tile 128x128, K-chunk 64 (128B SW128 rows), 4 chunks, 3-stage
// cp.async pipeline (wait_group 1), 1 syncthreads/chunk.
// 8 warps: warp_m = wid&3 (32 rows), warp_n = wid>>2 (64 cols), warp tile 32x64.
template <int RELU, int HOUT>
__global__ __launch_bounds__(256) void k_tc(
    const __half* __restrict__ A, const __half* __restrict__ B,
    const float* __restrict__ bias, void* __restrict__ Cv,
    int M, const int* __restrict__ dM, int N)
{
    extern __shared__ __align__(1024) char dsm[];  // 3 x (16KB A + 16KB B)
    int Meff = dM ? *dM : M;
    int m0 = blockIdx.y * 128;
    if (m0 >= Meff) return;
    int n0 = blockIdx.x * 128;

    int tid = threadIdx.x, wid = tid >> 5, lane = tid & 31;
    int warp_m = wid & 3, warp_n = wid >> 2;
    uint32_t sb = smem_to_u32(dsm);

    int lrow = tid >> 1;   // 0..127
    int lhalf = tid & 1;   // 64B half of the 128B row

    auto load_chunk = [&](int c, int b) {
        int kofs = c * 64;
        uint32_t baseA = sb + b * 32768;
        uint32_t baseB = baseA + 16384;
        {
            int r = m0 + lrow;
            int v = (r < Meff) ? 16 : 0;
            int rs = (r < Meff) ? r : 0;
            const __half* ap = A + (size_t)rs * DIM + kofs + lhalf * 32;
#pragma unroll
            for (int i = 0; i < 4; i++) {
                uint32_t off = (uint32_t)lrow * 128 + lhalf * 64 + i * 16;
                cp_async16(baseA + SWZ(off), ap + i * 8, v);
            }
        }
        {
            const __half* bp = B + (size_t)(n0 + lrow) * DIM + kofs + lhalf * 32;
#pragma unroll
            for (int i = 0; i < 4; i++) {
                uint32_t off = (uint32_t)lrow * 128 + lhalf * 64 + i * 16;
                cp_async16(baseB + SWZ(off), bp + i * 8, 16);
            }
        }
    };

    float acc[2][8][4];
#pragma unroll
    for (int mt = 0; mt < 2; mt++)
#pragma unroll
        for (int nt = 0; nt < 8; nt++)
#pragma unroll
            for (int e = 0; e < 4; e++) acc[mt][nt][e] = 0.f;

    load_chunk(0, 0); cp_commit();
    load_chunk(1, 1); cp_commit();

    for (int c = 0; c < 4; c++) {
        if (c + 1 < 4) cp_wait1(); else cp_wait0();
        __syncthreads();
        if (c + 2 < 4) { load_chunk(c + 2, (c + 2) % 3); cp_commit(); }

        uint32_t baseA = sb + (c % 3) * 32768;
        uint32_t baseB = baseA + 16384;
        int lr16 = lane & 15;
        int lk = (lane >> 4) * 16;

#pragma unroll
        for (int ks = 0; ks < 4; ks++) {
            int kb = ks * 32 + lk;
            uint32_t a[2][4];
#pragma unroll
            for (int mt = 0; mt < 2; mt++) {
                uint32_t off = (uint32_t)(warp_m * 32 + mt * 16 + lr16) * 128 + kb;
                ldsm_x4(a[mt][0], a[mt][1], a[mt][2], a[mt][3], baseA + SWZ(off));
            }
            uint32_t bfr[4][4];
#pragma unroll
            for (int ng = 0; ng < 4; ng++) {
                uint32_t off = (uint32_t)(warp_n * 64 + ng * 16 + lr16) * 128 + kb;
                ldsm_x4(bfr[ng][0], bfr[ng][1], bfr[ng][2], bfr[ng][3], baseB + SWZ(off));
            }
#pragma unroll
            for (int mt = 0; mt < 2; mt++)
#pragma unroll
                for (int ng = 0; ng < 4; ng++) {
                    mma_f16(acc[mt][2 * ng],     a[mt], bfr[ng][0], bfr[ng][2]);
                    mma_f16(acc[mt][2 * ng + 1], a[mt], bfr[ng][1], bfr[ng][3]);
                }
        }
    }

    int gr = lane >> 2, gc = (lane & 3) * 2;
#pragma unroll
    for (int mt = 0; mt < 2; mt++) {
#pragma unroll
        for (int nt = 0; nt < 8; nt++) {
            int col = n0 + warp_n * 64 + nt * 8 + gc;
            float b0 = bias[col], b1 = bias[col + 1];
            int r0 = m0 + warp_m * 32 + mt * 16 + gr;
            int r1 = r0 + 8;
#pragma unroll
            for (int half = 0; half < 2; half++) {
                int r = half ? r1 : r0;
                if (r >= Meff) continue;
                float vx = acc[mt][nt][2 * half + 0] + b0;
                float vy = acc[mt][nt][2 * half + 1] + b1;
                if (RELU) { vx = fmaxf(vx, 0.f); vy = fmaxf(vy, 0.f); }
                if (HOUT) {
                    __half* C = (__half*)Cv;
                    *(__half2*)(C + (size_t)r * N + col) = __floats2half2_rn(vx, vy);
                } else {
                    float* C = (float*)Cv;
                    *(float2*)(C + (size_t)r * N + col) = make_float2(vx, vy);
                }
            }
        }
    }
}

// ---------------- scatter-mean gather (fp16 Y) -> compact fp16 profile rows ----------------
__global__ void k_profile() {
    int w = (blockIdx.x * blockDim.x + threadIdx.x) >> 5;
    int lane = threadIdx.x & 31;
    if (w >= g_nm) return;
    int o = g_list[w];
    int beg = g_off[o];
    int c = g_cnt[o];
    float s[8] = {0, 0, 0, 0, 0, 0, 0, 0};
    const uint4* Y4 = (const uint4*)g_Y;   // 8 halves per lane
    for (int i = 0; i < c; i++) {
        int e = g_sortedEvt[beg + i];
        uint4 v = Y4[(size_t)e * 32 + lane];
        float2 p0 = __half22float2(*(__half2*)&v.x);
        float2 p1 = __half22float2(*(__half2*)&v.y);
        float2 p2 = __half22float2(*(__half2*)&v.z);
        float2 p3 = __half22float2(*(__half2*)&v.w);
        s[0] += p0.x; s[1] += p0.y; s[2] += p1.x; s[3] += p1.y;
        s[4] += p2.x; s[5] += p2.y; s[6] += p3.x; s[7] += p3.y;
    }
    float inv = 1.f / fmaxf((float)c, 1.f);
    uint4 hv;
    hv.x = h2u(__floats2half2_rn(s[0] * inv, s[1] * inv));
    hv.y = h2u(__floats2half2_rn(s[2] * inv, s[3] * inv));
    hv.z = h2u(__floats2half2_rn(s[4] * inv, s[5] * inv));
    hv.w = h2u(__floats2half2_rn(s[6] * inv, s[7] * inv));
    ((uint4*)g_P16)[(size_t)w * 32 + lane] = hv;
}

// gather objX rows for masked objects -> compact fp16
__global__ void k_convO(const float* __restrict__ objX) {
    int idx = blockIdx.x * blockDim.x + threadIdx.x;
    int r = idx >> 5, lane = idx & 31;
    if (r >= g_nm) return;
    int o = g_list[r];
    float4 a = ((const float4*)objX)[(size_t)o * 64 + lane * 2];
    float4 b = ((const float4*)objX)[(size_t)o * 64 + lane * 2 + 1];
    uint4 hv;
    hv.x = h2u(__floats2half2_rn(a.x, a.y));
    hv.y = h2u(__floats2half2_rn(a.z, a.w));
    hv.z = h2u(__floats2half2_rn(b.x, b.y));
    hv.w = h2u(__floats2half2_rn(b.z, b.w));
    ((uint4*)g_O16)[(size_t)r * 32 + lane] = hv;
}

// ---------------- fused output: masked rows -> GRU, others -> copy ----------------
__global__ void k_out(const float* __restrict__ objX, float* __restrict__ out) {
    int o = blockIdx.x;
    int c = threadIdx.x;  // 256
    float h = objX[(size_t)o * DIM + c];
    if (g_mask[o]) {
        int r = g_rowof[o];
        const __half* gi = g_GIh + (size_t)r * 768;
        const __half* gh = g_GHh + (size_t)r * 768;
        float ir = __half2float(gi[c]);
        float iz = __half2float(gi[c + 256]);
        float in_ = __half2float(gi[c + 512]);
        float hr = __half2float(gh[c]);
        float hz = __half2float(gh[c + 256]);
        float hn = __half2float(gh[c + 512]);
        float rg = 1.f / (1.f + __expf(-(ir + hr)));
        float z  = 1.f / (1.f + __expf(-(iz + hz)));
        float n  = tanhf(in_ + rg * hn);
        out[(size_t)o * DIM + c] = (1.f - z) * n + z * h;
    } else {
        out[(size_t)o * DIM + c] = h;
    }
}

// ---------------- launch ----------------
extern "C" void kernel_launch(void* const* d_in, const int* in_sizes, int n_in,
                              void* d_out, int out_size) {
    const float* objX  = (const float*)d_in[0];
    const float* evtX  = (const float*)d_in[1];
    const int*   obj_i = (const int*)d_in[2];
    const int*   evt_i = (const int*)d_in[3];
    const int*   m_idx = (const int*)d_in[4];
    const float* Wp    = (const float*)d_in[5];
    const float* bp    = (const float*)d_in[6];
    const float* Wih   = (const float*)d_in[7];
    const float* bih   = (const float*)d_in[8];
    const float* Whh   = (const float*)d_in[9];
    const float* bhh   = (const float*)d_in[10];
    float* out = (float*)d_out;

    int n_obj  = in_sizes[0] / DIM;
    int n_evt  = in_sizes[1] / DIM;
    int n_edge = in_sizes[2];
    int n_main = in_sizes[4];
    int worstM = (n_main < n_obj) ? n_main : n_obj;

    __half *pE16, *pY, *pP16, *pO16, *pWp16, *pWih16, *pWhh16, *pGIh, *pGHh;
    int *pNM;
    cudaGetSymbolAddress((void**)&pE16, g_E16);
    cudaGetSymbolAddress((void**)&pY, g_Y);
    cudaGetSymbolAddress((void**)&pP16, g_P16);
    cudaGetSymbolAddress((void**)&pO16, g_O16);
    cudaGetSymbolAddress((void**)&pWp16, g_Wp16);
    cudaGetSymbolAddress((void**)&pWih16, g_Wih16);
    cudaGetSymbolAddress((void**)&pWhh16, g_Whh16);
    cudaGetSymbolAddress((void**)&pGIh, g_GIh);
    cudaGetSymbolAddress((void**)&pGHh, g_GHh);
    cudaGetSymbolAddress((void**)&pNM, g_nm);

    const int SMEM_BYTES = 3 * 32768;  // 96KB, 3-stage
    cudaFuncSetAttribute(k_tc<0, 1>, cudaFuncAttributeMaxDynamicSharedMemorySize, SMEM_BYTES);
    cudaFuncSetAttribute(k_tc<1, 1>, cudaFuncAttributeMaxDynamicSharedMemorySize, SMEM_BYTES);

    // 1. bookkeeping + fp16 conversions
    k_zero<<<(n_obj + 255) / 256, 256>>>(n_obj);
    k_cvt16<<<(n_evt * DIM / 8 + 255) / 256, 256>>>(evtX, pE16, n_evt * DIM / 8);
    k_cvt16<<<(DIM * DIM / 8 + 255) / 256, 256>>>(Wp, pWp16, DIM * DIM / 8);
    k_cvt16<<<(768 * DIM / 8 + 255) / 256, 256>>>(Wih, pWih16, 768 * DIM / 8);
    k_cvt16<<<(768 * DIM / 8 + 255) / 256, 256>>>(Whh, pWhh16, 768 * DIM / 8);

    // 2. Y = relu(event_X @ Wp^T + bp), fp16 output
    {
        dim3 g(DIM / 128, (n_evt + 127) / 128);
        k_tc<1, 1><<<g, 256, SMEM_BYTES>>>(pE16, pWp16, bp, pY, n_evt, nullptr, DIM);
    }

    // 3. CSR build
    k_count<<<(n_edge + 255) / 256, 256>>>(obj_i, n_edge);
    int nb = (n_obj + 1023) / 1024;
    k_scan1<<<nb, 1024>>>(n_obj);
    k_scan2<<<1, 32>>>(nb);
    k_scan3<<<(n_obj + 255) / 256, 256>>>(n_obj);
    k_fill<<<(n_edge + 255) / 256, 256>>>(obj_i, evt_i, n_edge);

    // 4. compact unique masked objects (+ row map)
    k_list<<<(n_main + 255) / 256, 256>>>(m_idx, n_main);

    // 5. scatter-mean gather + objX gather (compact fp16)
    k_profile<<<(worstM * 32 + 255) / 256, 256>>>();
    k_convO<<<(worstM * 32 + 255) / 256, 256>>>(objX);

    // 6. GRU GEMMs over compact rows (fp16 gate output)
    {
        dim3 g(768 / 128, (worstM + 127) / 128);
        k_tc<0, 1><<<g, 256, SMEM_BYTES>>>(pP16, pWih16, bih, pGIh, worstM, pNM, 768);
        k_tc<0, 1><<<g, 256, SMEM_BYTES>>>(pO16, pWhh16, bhh, pGHh, worstM, pNM, 768);
    }

    // 7. fused output: GRU for masked rows, copy otherwise
    k_out<<<n_obj, DIM>>>(objX, out);
}

// round 17
// speedup vs baseline: 6.1831x; 1.0220x over previous
#include <cuda_runtime.h>
#include <cuda_fp16.h>
#include <cstdint>

#define NOBJ_MAX 50000
#define NEVT_MAX 100000
#define NEDGE_MAX 500000
#define DIM 256

// ---------------- static scratch (zero-initialized at load; k_out tail-resets) ----------------
__device__ __align__(16) __half g_E16[NEVT_MAX * DIM];   // event_X fp16
__device__ __align__(16) __half g_Y[NEVT_MAX * DIM];     // relu(event_X @ Wp^T + bp), fp16
__device__ __align__(16) __half g_P16[NOBJ_MAX * DIM];   // compact profile rows fp16
__device__ __align__(16) __half g_O16[NOBJ_MAX * DIM];   // compact objX rows fp16
__device__ __align__(16) __half g_Wp16[DIM * DIM];
__device__ __align__(16) __half g_Wih16[768 * DIM];
__device__ __align__(16) __half g_Whh16[768 * DIM];
__device__ __align__(16) __half g_GIh[NOBJ_MAX * 768];   // gi gates fp16
__device__ __align__(16) __half g_GHh[NOBJ_MAX * 768];   // gh gates fp16
__device__ int g_cnt[NOBJ_MAX];      // zeroed at load; re-zeroed by k_out tail
__device__ int g_off[NOBJ_MAX];
__device__ int g_cur[NOBJ_MAX];      // zeroed at load; re-zeroed by k_out tail
__device__ int g_mask[NOBJ_MAX];     // zeroed at load; re-zeroed by k_out tail
__device__ int g_list[NOBJ_MAX];
__device__ int g_rowof[NOBJ_MAX];
__device__ int g_sortedEvt[NEDGE_MAX];
__device__ int g_bsum[64];
__device__ int g_nm;                 // zeroed at load; re-zeroed by k_out tail

// ---------------- PTX helpers (sm_80-portable only) ----------------
__device__ __forceinline__ uint32_t smem_to_u32(const void* p) {
    uint32_t a;
    asm("{ .reg .u64 t; cvta.to.shared.u64 t, %1; cvt.u32.u64 %0, t; }"
        : "=r"(a) : "l"(p));
    return a;
}
__device__ __forceinline__ void cp_async16(uint32_t dst, const void* src, int src_bytes) {
    asm volatile("cp.async.cg.shared.global [%0], [%1], 16, %2;"
                 :: "r"(dst), "l"(src), "r"(src_bytes) : "memory");
}
__device__ __forceinline__ void cp_commit() {
    asm volatile("cp.async.commit_group;" ::: "memory");
}
__device__ __forceinline__ void cp_wait0() {
    asm volatile("cp.async.wait_group 0;" ::: "memory");
}
__device__ __forceinline__ void cp_wait1() {
    asm volatile("cp.async.wait_group 1;" ::: "memory");
}
__device__ __forceinline__ void ldsm_x4(uint32_t& r0, uint32_t& r1, uint32_t& r2, uint32_t& r3,
                                        uint32_t addr) {
    asm volatile("ldmatrix.sync.aligned.m8n8.x4.shared.b16 {%0,%1,%2,%3}, [%4];"
                 : "=r"(r0), "=r"(r1), "=r"(r2), "=r"(r3) : "r"(addr));
}
__device__ __forceinline__ void mma_f16(float* d, const uint32_t* a,
                                        uint32_t b0, uint32_t b1) {
    asm volatile("mma.sync.aligned.m16n8k16.row.col.f32.f16.f16.f32 "
                 "{%0,%1,%2,%3}, {%4,%5,%6,%7}, {%8,%9}, {%0,%1,%2,%3};"
                 : "+f"(d[0]), "+f"(d[1]), "+f"(d[2]), "+f"(d[3])
                 : "r"(a[0]), "r"(a[1]), "r"(a[2]), "r"(a[3]), "r"(b0), "r"(b1));
}

#define SWZ(o) ((o) ^ (((o) >> 3) & 0x70))

__device__ __forceinline__ uint32_t h2u(__half2 h) {
    union { __half2 h; uint32_t u; } cv; cv.h = h; return cv.u;
}

// ---------------- small utility kernels ----------------
__global__ void k_count(const int* __restrict__ obj, int n) {
    int i = blockIdx.x * blockDim.x + threadIdx.x;
    if (i < n) atomicAdd(&g_cnt[obj[i]], 1);
}
__global__ void k_scan1(int n) {
    __shared__ int s[1024];
    int t = threadIdx.x;
    int i = blockIdx.x * 1024 + t;
    int v = (i < n) ? g_cnt[i] : 0;
    s[t] = v; __syncthreads();
    for (int d = 1; d < 1024; d <<= 1) {
        int x = (t >= d) ? s[t - d] : 0;
        __syncthreads();
        s[t] += x;
        __syncthreads();
    }
    if (i < n) g_off[i] = s[t] - v;
    if (t == 1023) g_bsum[blockIdx.x] = s[1023];
}
__global__ void k_scan2(int nb) {
    if (threadIdx.x == 0 && blockIdx.x == 0) {
        int run = 0;
        for (int b = 0; b < nb; b++) { int t = g_bsum[b]; g_bsum[b] = run; run += t; }
    }
}
__global__ void k_scan3(int n) {
    int i = blockIdx.x * blockDim.x + threadIdx.x;
    if (i < n) g_off[i] += g_bsum[i >> 10];
}
__global__ void k_fill(const int* __restrict__ obj, const int* __restrict__ evt, int n) {
    int i = blockIdx.x * blockDim.x + threadIdx.x;
    if (i < n) {
        int o = obj[i];
        int p = atomicAdd(&g_cur[o], 1);
        g_sortedEvt[g_off[o] + p] = evt[i];
    }
}
__global__ void k_list(const int* __restrict__ midx, int n) {
    int i = blockIdx.x * blockDim.x + threadIdx.x;
    if (i < n) {
        int o = midx[i];
        if (atomicExch(&g_mask[o], 1) == 0) {
            int p = atomicAdd(&g_nm, 1);
            g_list[p] = o;
            g_rowof[o] = p;
        }
    }
}

// fused fp32 -> fp16 converts: evtX, Wp, Wih, Whh in one launch (8 floats/thread)
__global__ void k_cvtAll(const float* __restrict__ evtX, __half* __restrict__ E16, int nE8,
                         const float* __restrict__ Wp, __half* __restrict__ Wp16, int nWp8,
                         const float* __restrict__ Wih, __half* __restrict__ Wih16, int nWih8,
                         const float* __restrict__ Whh, __half* __restrict__ Whh16, int nWhh8) {
    int i = blockIdx.x * blockDim.x + threadIdx.x;
    const float* src; __half* dst; int j;
    if (i < nE8) { src = evtX; dst = E16; j = i; }
    else if (i < nE8 + nWp8) { src = Wp; dst = Wp16; j = i - nE8; }
    else if (i < nE8 + nWp8 + nWih8) { src = Wih; dst = Wih16; j = i - nE8 - nWp8; }
    else if (i < nE8 + nWp8 + nWih8 + nWhh8) { src = Whh; dst = Whh16; j = i - nE8 - nWp8 - nWih8; }
    else return;
    float4 a = ((const float4*)src)[2 * j];
    float4 b = ((const float4*)src)[2 * j + 1];
    uint4 hv;
    hv.x = h2u(__floats2half2_rn(a.x, a.y));
    hv.y = h2u(__floats2half2_rn(a.z, a.w));
    hv.z = h2u(__floats2half2_rn(b.x, b.y));
    hv.w = h2u(__floats2half2_rn(b.z, b.w));
    ((uint4*)dst)[j] = hv;
}

// ---------------- mma.sync fp16 GEMM: C = A @ B^T + bias ----------------
// A: [M,256] fp16; B: [N,256] fp16; C: [M,N] fp32 or fp16 (HOUT).
// Block tile 128x128, K-chunk 64 (128B SW128 rows), 4 chunks, 3-stage
// cp.async pipeline (wait_group 1), 1 syncthreads/chunk.
// 8 warps: warp_m = wid&3 (32 rows), warp_n = wid>>2 (64 cols), warp tile 32x64.
template <int RELU, int HOUT>
__global__ __launch_bounds__(256) void k_tc(
    const __half* __restrict__ A, const __half* __restrict__ B,
    const float* __restrict__ bias, void* __restrict__ Cv,
    int M, const int* __restrict__ dM, int N)
{
    extern __shared__ __align__(1024) char dsm[];  // 3 x (16KB A + 16KB B)
    int Meff = dM ? *dM : M;
    int m0 = blockIdx.y * 128;
    if (m0 >= Meff) return;
    int n0 = blockIdx.x * 128;

    int tid = threadIdx.x, wid = tid >> 5, lane = tid & 31;
    int warp_m = wid & 3, warp_n = wid >> 2;
    uint32_t sb = smem_to_u32(dsm);

    int lrow = tid >> 1;   // 0..127
    int lhalf = tid & 1;   // 64B half of the 128B row

    auto load_chunk = [&](int c, int b) {
        int kofs = c * 64;
        uint32_t baseA = sb + b * 32768;
        uint32_t baseB = baseA + 16384;
        {
            int r = m0 + lrow;
            int v = (r < Meff) ? 16 : 0;
            int rs = (r < Meff) ? r : 0;
            const __half* ap = A + (size_t)rs * DIM + kofs + lhalf * 32;
#pragma unroll
            for (int i = 0; i < 4; i++) {
                uint32_t off = (uint32_t)lrow * 128 + lhalf * 64 + i * 16;
                cp_async16(baseA + SWZ(off), ap + i * 8, v);
            }
        }
        {
            const __half* bp = B + (size_t)(n0 + lrow) * DIM + kofs + lhalf * 32;
#pragma unroll
            for (int i = 0; i < 4; i++) {
                uint32_t off = (uint32_t)lrow * 128 + lhalf * 64 + i * 16;
                cp_async16(baseB + SWZ(off), bp + i * 8, 16);
            }
        }
    };

    float acc[2][8][4];
#pragma unroll
    for (int mt = 0; mt < 2; mt++)
#pragma unroll
        for (int nt = 0; nt < 8; nt++)
#pragma unroll
            for (int e = 0; e < 4; e++) acc[mt][nt][e] = 0.f;

    load_chunk(0, 0); cp_commit();
    load_chunk(1, 1); cp_commit();

    for (int c = 0; c < 4; c++) {
        if (c + 1 < 4) cp_wait1(); else cp_wait0();
        __syncthreads();
        if (c + 2 < 4) { load_chunk(c + 2, (c + 2) % 3); cp_commit(); }

        uint32_t baseA = sb + (c % 3) * 32768;
        uint32_t baseB = baseA + 16384;
        int lr16 = lane & 15;
        int lk = (lane >> 4) * 16;

#pragma unroll
        for (int ks = 0; ks < 4; ks++) {
            int kb = ks * 32 + lk;
            uint32_t a[2][4];
#pragma unroll
            for (int mt = 0; mt < 2; mt++) {
                uint32_t off = (uint32_t)(warp_m * 32 + mt * 16 + lr16) * 128 + kb;
                ldsm_x4(a[mt][0], a[mt][1], a[mt][2], a[mt][3], baseA + SWZ(off));
            }
            uint32_t bfr[4][4];
#pragma unroll
            for (int ng = 0; ng < 4; ng++) {
                uint32_t off = (uint32_t)(warp_n * 64 + ng * 16 + lr16) * 128 + kb;
                ldsm_x4(bfr[ng][0], bfr[ng][1], bfr[ng][2], bfr[ng][3], baseB + SWZ(off));
            }
#pragma unroll
            for (int mt = 0; mt < 2; mt++)
#pragma unroll
                for (int ng = 0; ng < 4; ng++) {
                    mma_f16(acc[mt][2 * ng],     a[mt], bfr[ng][0], bfr[ng][2]);
                    mma_f16(acc[mt][2 * ng + 1], a[mt], bfr[ng][1], bfr[ng][3]);
                }
        }
    }

    int gr = lane >> 2, gc = (lane & 3) * 2;
#pragma unroll
    for (int mt = 0; mt < 2; mt++) {
#pragma unroll
        for (int nt = 0; nt < 8; nt++) {
            int col = n0 + warp_n * 64 + nt * 8 + gc;
            float b0 = bias[col], b1 = bias[col + 1];
            int r0 = m0 + warp_m * 32 + mt * 16 + gr;
            int r1 = r0 + 8;
#pragma unroll
            for (int half = 0; half < 2; half++) {
                int r = half ? r1 : r0;
                if (r >= Meff) continue;
                float vx = acc[mt][nt][2 * half + 0] + b0;
                float vy = acc[mt][nt][2 * half + 1] + b1;
                if (RELU) { vx = fmaxf(vx, 0.f); vy = fmaxf(vy, 0.f); }
                if (HOUT) {
                    __half* C = (__half*)Cv;
                    *(__half2*)(C + (size_t)r * N + col) = __floats2half2_rn(vx, vy);
                } else {
                    float* C = (float*)Cv;
                    *(float2*)(C + (size_t)r * N + col) = make_float2(vx, vy);
                }
            }
        }
    }
}

// ---------------- fused: scatter-mean gather (fp16 Y) + objX gather -> compact fp16 rows ----------------
__global__ void k_profconv(const float* __restrict__ objX) {
    int w = (blockIdx.x * blockDim.x + threadIdx.x) >> 5;
    int lane = threadIdx.x & 31;
    if (w >= g_nm) return;
    int o = g_list[w];

    // objX gather -> O16
    {
        float4 a = ((const float4*)objX)[(size_t)o * 64 + lane * 2];
        float4 b = ((const float4*)objX)[(size_t)o * 64 + lane * 2 + 1];
        uint4 hv;
        hv.x = h2u(__floats2half2_rn(a.x, a.y));
        hv.y = h2u(__floats2half2_rn(a.z, a.w));
        hv.z = h2u(__floats2half2_rn(b.x, b.y));
        hv.w = h2u(__floats2half2_rn(b.z, b.w));
        ((uint4*)g_O16)[(size_t)w * 32 + lane] = hv;
    }

    // scatter-mean over incident events -> P16
    int beg = g_off[o];
    int c = g_cnt[o];
    float s[8] = {0, 0, 0, 0, 0, 0, 0, 0};
    const uint4* Y4 = (const uint4*)g_Y;   // 8 halves per lane
    for (int i = 0; i < c; i++) {
        int e = g_sortedEvt[beg + i];
        uint4 v = Y4[(size_t)e * 32 + lane];
        float2 p0 = __half22float2(*(__half2*)&v.x);
        float2 p1 = __half22float2(*(__half2*)&v.y);
        float2 p2 = __half22float2(*(__half2*)&v.z);
        float2 p3 = __half22float2(*(__half2*)&v.w);
        s[0] += p0.x; s[1] += p0.y; s[2] += p1.x; s[3] += p1.y;
        s[4] += p2.x; s[5] += p2.y; s[6] += p3.x; s[7] += p3.y;
    }
    float inv = 1.f / fmaxf((float)c, 1.f);
    uint4 hv;
    hv.x = h2u(__floats2half2_rn(s[0] * inv, s[1] * inv));
    hv.y = h2u(__floats2half2_rn(s[2] * inv, s[3] * inv));
    hv.z = h2u(__floats2half2_rn(s[4] * inv, s[5] * inv));
    hv.w = h2u(__floats2half2_rn(s[6] * inv, s[7] * inv));
    ((uint4*)g_P16)[(size_t)w * 32 + lane] = hv;
}

// ---------------- fused output + tail reset: masked rows -> GRU, others -> copy ----------------
__global__ void k_out(const float* __restrict__ objX, float* __restrict__ out) {
    int o = blockIdx.x;
    int c = threadIdx.x;  // 256
    float h = objX[(size_t)o * DIM + c];
    int m = g_mask[o];
    if (m) {
        int r = g_rowof[o];
        const __half* gi = g_GIh + (size_t)r * 768;
        const __half* gh = g_GHh + (size_t)r * 768;
        float ir = __half2float(gi[c]);
        float iz = __half2float(gi[c + 256]);
        float in_ = __half2float(gi[c + 512]);
        float hr = __half2float(gh[c]);
        float hz = __half2float(gh[c + 256]);
        float hn = __half2float(gh[c + 512]);
        float rg = 1.f / (1.f + __expf(-(ir + hr)));
        float z  = 1.f / (1.f + __expf(-(iz + hz)));
        float n  = tanhf(in_ + rg * hn);
        out[(size_t)o * DIM + c] = (1.f - z) * n + z * h;
    } else {
        out[(size_t)o * DIM + c] = h;
    }
    // tail reset so the next replay starts from a clean state
    __syncthreads();
    if (c == 0) {
        g_cnt[o] = 0; g_cur[o] = 0; g_mask[o] = 0;
        if (o == 0) g_nm = 0;
    }
}

// ---------------- launch ----------------
extern "C" void kernel_launch(void* const* d_in, const int* in_sizes, int n_in,
                              void* d_out, int out_size) {
    const float* objX  = (const float*)d_in[0];
    const float* evtX  = (const float*)d_in[1];
    const int*   obj_i = (const int*)d_in[2];
    const int*   evt_i = (const int*)d_in[3];
    const int*   m_idx = (const int*)d_in[4];
    const float* Wp    = (const float*)d_in[5];
    const float* bp    = (const float*)d_in[6];
    const float* Wih   = (const float*)d_in[7];
    const float* bih   = (const float*)d_in[8];
    const float* Whh   = (const float*)d_in[9];
    const float* bhh   = (const float*)d_in[10];
    float* out = (float*)d_out;

    int n_obj  = in_sizes[0] / DIM;
    int n_evt  = in_sizes[1] / DIM;
    int n_edge = in_sizes[2];
    int n_main = in_sizes[4];
    int worstM = (n_main < n_obj) ? n_main : n_obj;

    __half *pE16, *pY, *pP16, *pO16, *pWp16, *pWih16, *pWhh16, *pGIh, *pGHh;
    int *pNM;
    cudaGetSymbolAddress((void**)&pE16, g_E16);
    cudaGetSymbolAddress((void**)&pY, g_Y);
    cudaGetSymbolAddress((void**)&pP16, g_P16);
    cudaGetSymbolAddress((void**)&pO16, g_O16);
    cudaGetSymbolAddress((void**)&pWp16, g_Wp16);
    cudaGetSymbolAddress((void**)&pWih16, g_Wih16);
    cudaGetSymbolAddress((void**)&pWhh16, g_Whh16);
    cudaGetSymbolAddress((void**)&pGIh, g_GIh);
    cudaGetSymbolAddress((void**)&pGHh, g_GHh);
    cudaGetSymbolAddress((void**)&pNM, g_nm);

    const int SMEM_BYTES = 3 * 32768;  // 96KB, 3-stage
    cudaFuncSetAttribute(k_tc<0, 1>, cudaFuncAttributeMaxDynamicSharedMemorySize, SMEM_BYTES);
    cudaFuncSetAttribute(k_tc<1, 1>, cudaFuncAttributeMaxDynamicSharedMemorySize, SMEM_BYTES);

    // 1. fused fp16 conversions (evtX, Wp, Wih, Whh)
    int nE8 = n_evt * DIM / 8;
    int nWp8 = DIM * DIM / 8;
    int nW8 = 768 * DIM / 8;
    int nTot = nE8 + nWp8 + 2 * nW8;
    k_cvtAll<<<(nTot + 255) / 256, 256>>>(evtX, pE16, nE8, Wp, pWp16, nWp8,
                                          Wih, pWih16, nW8, Whh, pWhh16, nW8);

    // 2. Y = relu(event_X @ Wp^T + bp), fp16 output
    {
        dim3 g(DIM / 128, (n_evt + 127) / 128);
        k_tc<1, 1><<<g, 256, SMEM_BYTES>>>(pE16, pWp16, bp, pY, n_evt, nullptr, DIM);
    }

    // 3. CSR build (cnt/cur zeroed by previous k_out tail / static init)
    k_count<<<(n_edge + 255) / 256, 256>>>(obj_i, n_edge);
    int nb = (n_obj + 1023) / 1024;
    k_scan1<<<nb, 1024>>>(n_obj);
    k_scan2<<<1, 32>>>(nb);
    k_scan3<<<(n_obj + 255) / 256, 256>>>(n_obj);
    k_fill<<<(n_edge + 255) / 256, 256>>>(obj_i, evt_i, n_edge);

    // 4. compact unique masked objects (+ row map); mask/nm pre-zeroed
    k_list<<<(n_main + 255) / 256, 256>>>(m_idx, n_main);

    // 5. fused scatter-mean + objX gather (compact fp16 rows)
    k_profconv<<<(worstM * 32 + 255) / 256, 256>>>(objX);

    // 6. GRU GEMMs over compact rows (fp16 gate output)
    {
        dim3 g(768 / 128, (worstM + 127) / 128);
        k_tc<0, 1><<<g, 256, SMEM_BYTES>>>(pP16, pWih16, bih, pGIh, worstM, pNM, 768);
        k_tc<0, 1><<<g, 256, SMEM_BYTES>>>(pO16, pWhh16, bhh, pGHh, worstM, pNM, 768);
    }

    // 7. fused output (GRU for masked rows, copy otherwise) + tail state reset
    k_out<<<n_obj, DIM>>>(objX, out);
}